// round 1
// baseline (speedup 1.0000x reference)
#include <cuda_runtime.h>

// Problem constants
#define BATCH   2
#define SEQ     2048
#define DIMM    1024
#define NHEAD   16
#define HDIM    64

// ---------------- scratch (allocation-free: device globals) ----------------
static __device__ float g_qh[BATCH * NHEAD * SEQ * HDIM];
static __device__ float g_kh[BATCH * NHEAD * SEQ * HDIM];
static __device__ float g_vh[BATCH * NHEAD * SEQ * HDIM];
static __device__ float g_ao[BATCH * NHEAD * SEQ * HDIM];

// ---------------- SGEMM: 128x128 tile, 8x8 micro, BK=16 --------------------
// MODE 0: projection  C_scatter[b,h,s,e] = A[4096,1024] * W(head-blocked [H,K,64])
// MODE 1: plain       C[4096,1024]       = A[4096,1024] * W[1024,1024]
#define GM 4096
#define GN 1024
#define GK 1024
#define BM 128
#define BN 128
#define BKK 16

template <int MODE>
__global__ __launch_bounds__(256)
void sgemm_kernel(const float* __restrict__ A, const float* __restrict__ W,
                  float* __restrict__ C)
{
    __shared__ float As[BKK][BM];
    __shared__ float Bs[BKK][BN];

    const int tid = threadIdx.x;
    const int m0 = blockIdx.x * BM;
    const int n0 = blockIdx.y * BN;
    const int tx = tid & 15;
    const int ty = tid >> 4;

    float acc[8][8];
#pragma unroll
    for (int i = 0; i < 8; i++)
#pragma unroll
        for (int j = 0; j < 8; j++) acc[i][j] = 0.f;

    for (int k0 = 0; k0 < GK; k0 += BKK) {
        // Load A tile (128 x 16) as float4, store transposed
#pragma unroll
        for (int p = 0; p < 2; p++) {
            int slot = tid + p * 256;          // 0..511
            int row  = slot >> 2;              // 0..127
            int kq   = (slot & 3) * 4;         // 0,4,8,12
            float4 v = *(const float4*)(A + (size_t)(m0 + row) * GK + k0 + kq);
            As[kq + 0][row] = v.x;
            As[kq + 1][row] = v.y;
            As[kq + 2][row] = v.z;
            As[kq + 3][row] = v.w;
        }
        // Load B tile (16 x 128) as float4
#pragma unroll
        for (int p = 0; p < 2; p++) {
            int slot = tid + p * 256;          // 0..511
            int kk   = slot >> 5;              // 0..15
            int c4   = (slot & 31) * 4;        // 0..124
            float4 v;
            if (MODE == 0) {
                int col = n0 + c4;
                int hh = col >> 6, e = col & 63;   // 4 cols stay in one head block
                v = *(const float4*)(W + ((size_t)hh * GK + (k0 + kk)) * 64 + e);
            } else {
                v = *(const float4*)(W + (size_t)(k0 + kk) * GN + n0 + c4);
            }
            *(float4*)&Bs[kk][c4] = v;
        }
        __syncthreads();

#pragma unroll
        for (int kk = 0; kk < BKK; kk++) {
            float a[8], b[8];
            *(float4*)&a[0] = *(const float4*)&As[kk][ty * 8];
            *(float4*)&a[4] = *(const float4*)&As[kk][ty * 8 + 4];
            *(float4*)&b[0] = *(const float4*)&Bs[kk][tx * 8];
            *(float4*)&b[4] = *(const float4*)&Bs[kk][tx * 8 + 4];
#pragma unroll
            for (int i = 0; i < 8; i++)
#pragma unroll
                for (int j = 0; j < 8; j++)
                    acc[i][j] = fmaf(a[i], b[j], acc[i][j]);
        }
        __syncthreads();
    }

    if (MODE == 0) {
        // scatter into [B,H,S,hd]
#pragma unroll
        for (int i = 0; i < 8; i++) {
            int grow = m0 + ty * 8 + i;
            int bb = grow >> 11, s = grow & 2047;
#pragma unroll
            for (int j = 0; j < 8; j++) {
                int gcol = n0 + tx * 8 + j;
                int hh = gcol >> 6, e = gcol & 63;
                C[(((size_t)(bb * NHEAD + hh)) * SEQ + s) * HDIM + e] = acc[i][j];
            }
        }
    } else {
#pragma unroll
        for (int i = 0; i < 8; i++) {
            int grow = m0 + ty * 8 + i;
            float4 v0 = make_float4(acc[i][0], acc[i][1], acc[i][2], acc[i][3]);
            float4 v1 = make_float4(acc[i][4], acc[i][5], acc[i][6], acc[i][7]);
            *(float4*)(C + (size_t)grow * GN + n0 + tx * 8)     = v0;
            *(float4*)(C + (size_t)grow * GN + n0 + tx * 8 + 4) = v1;
        }
    }
}

// ---------------- Flash attention: TQ=128 rows / block, TK=64 --------------
#define TQ 128
#define TK 64
#define LD 65   // padded smem stride (bank-conflict avoidance)

// smem layout (floats): Qs[TQ*LD] Ks[TK*LD] Vs[TK*LD] Ps[TQ*LD] | km[TK] qm[TQ] (ints)
#define ATTN_SMEM_BYTES (((TQ + TK + TK + TQ) * LD) * 4 + (TK + TQ) * 4)

__global__ __launch_bounds__(256)
void attn_kernel(const float* __restrict__ QH, const float* __restrict__ KH,
                 const float* __restrict__ VH, const int* __restrict__ mask,
                 float* __restrict__ AO)
{
    extern __shared__ float sm[];
    float* Qs = sm;
    float* Ks = Qs + TQ * LD;
    float* Vs = Ks + TK * LD;
    float* Ps = Vs + TK * LD;
    int*   km = (int*)(Ps + TQ * LD);
    int*   qm = km + TK;

    const int b  = blockIdx.z;
    const int h  = blockIdx.y;
    const int q0 = blockIdx.x * TQ;
    const size_t base = ((size_t)(b * NHEAD + h)) * SEQ * HDIM;

    const int tid = threadIdx.x;
    const int tx = tid & 15;   // 16 col-threads
    const int ty = tid >> 4;   // 16 row-groups (8 rows each)

    // Load Q tile + row masks
    for (int idx = tid; idx < TQ * HDIM; idx += 256) {
        int r = idx >> 6, d = idx & 63;
        Qs[r * LD + d] = QH[base + (size_t)(q0 + r) * HDIM + d];
    }
    if (tid < TQ) qm[tid] = mask[b * SEQ + q0 + tid];

    const float NEGINF = __int_as_float(0xff800000u);
    float m[8], l[8], acc[8][4];
#pragma unroll
    for (int i = 0; i < 8; i++) {
        m[i] = NEGINF; l[i] = 0.f;
#pragma unroll
        for (int j = 0; j < 4; j++) acc[i][j] = 0.f;
    }

    const int ntiles = (q0 + TQ) / TK;
    for (int kt = 0; kt < ntiles; kt++) {
        const int t0 = kt * TK;
        __syncthreads();   // protects Ks/Vs reuse (and Q/qm visibility on kt=0)
        for (int idx = tid; idx < TK * HDIM; idx += 256) {
            int r = idx >> 6, d = idx & 63;
            Ks[r * LD + d] = KH[base + (size_t)(t0 + r) * HDIM + d];
            Vs[r * LD + d] = VH[base + (size_t)(t0 + r) * HDIM + d];
        }
        if (tid < TK) km[tid] = mask[b * SEQ + t0 + tid];
        __syncthreads();

        // scores: sc[i][j] = Q[ty*8+i] . K[tx*4+j]
        float sc[8][4];
#pragma unroll
        for (int i = 0; i < 8; i++)
#pragma unroll
            for (int j = 0; j < 4; j++) sc[i][j] = 0.f;

#pragma unroll 4
        for (int d = 0; d < HDIM; d++) {
            float qv[8], kv[4];
#pragma unroll
            for (int i = 0; i < 8; i++) qv[i] = Qs[(ty * 8 + i) * LD + d];
#pragma unroll
            for (int j = 0; j < 4; j++) kv[j] = Ks[(tx * 4 + j) * LD + d];
#pragma unroll
            for (int i = 0; i < 8; i++)
#pragma unroll
                for (int j = 0; j < 4; j++)
                    sc[i][j] = fmaf(qv[i], kv[j], sc[i][j]);
        }

        // mask + online softmax update
#pragma unroll
        for (int i = 0; i < 8; i++) {
            const int r = ty * 8 + i;
            const int sg = q0 + r;
            const bool mr = (qm[r] != 0);
            float mx = NEGINF;
#pragma unroll
            for (int j = 0; j < 4; j++) {
                int t = t0 + tx * 4 + j;
                // pad (row OR col masked) -> 0.0 ; causal overrides with -1e30
                float val = (mr || (km[tx * 4 + j] != 0)) ? 0.f : sc[i][j] * 0.125f;
                if (t > sg) val = -1e30f;
                sc[i][j] = val;
                mx = fmaxf(mx, val);
            }
#pragma unroll
            for (int off = 8; off; off >>= 1)
                mx = fmaxf(mx, __shfl_xor_sync(0xffffffffu, mx, off));
            float mn = fmaxf(m[i], mx);
            float corr = __expf(m[i] - mn);   // exp(-inf)=0 on first tile
            float rs = 0.f;
#pragma unroll
            for (int j = 0; j < 4; j++) {
                float p = __expf(sc[i][j] - mn);
                sc[i][j] = p;
                rs += p;
            }
#pragma unroll
            for (int off = 8; off; off >>= 1)
                rs += __shfl_xor_sync(0xffffffffu, rs, off);
            l[i] = l[i] * corr + rs;
            m[i] = mn;
#pragma unroll
            for (int j = 0; j < 4; j++) acc[i][j] *= corr;
            // P row is produced & consumed entirely within this half-warp
#pragma unroll
            for (int j = 0; j < 4; j++) Ps[r * LD + tx * 4 + j] = sc[i][j];
        }
        __syncwarp();

        // acc += P @ V
#pragma unroll 4
        for (int c = 0; c < TK; c++) {
            float vv[4];
#pragma unroll
            for (int j = 0; j < 4; j++) vv[j] = Vs[c * LD + tx * 4 + j];
#pragma unroll
            for (int i = 0; i < 8; i++) {
                float p = Ps[(ty * 8 + i) * LD + c];
#pragma unroll
                for (int j = 0; j < 4; j++)
                    acc[i][j] = fmaf(p, vv[j], acc[i][j]);
            }
        }
    }

    // epilogue: normalize and store [B,H,S,hd]
#pragma unroll
    for (int i = 0; i < 8; i++) {
        const int r = ty * 8 + i;
        const float inv = 1.f / l[i];
#pragma unroll
        for (int j = 0; j < 4; j++)
            AO[base + (size_t)(q0 + r) * HDIM + tx * 4 + j] = acc[i][j] * inv;
    }
}

// ---------------- launch ----------------------------------------------------
extern "C" void kernel_launch(void* const* d_in, const int* in_sizes, int n_in,
                              void* d_out, int out_size)
{
    const float* q    = (const float*)d_in[0];
    const float* k    = (const float*)d_in[1];
    const float* v    = (const float*)d_in[2];
    const float* Wq   = (const float*)d_in[3];
    const float* Wk   = (const float*)d_in[4];
    const float* Wv   = (const float*)d_in[5];
    const float* Wo   = (const float*)d_in[6];
    const int*   mask = (const int*)d_in[7];
    float* out = (float*)d_out;

    float *qh, *kh, *vh, *ao;
    cudaGetSymbolAddress((void**)&qh, g_qh);
    cudaGetSymbolAddress((void**)&kh, g_kh);
    cudaGetSymbolAddress((void**)&vh, g_vh);
    cudaGetSymbolAddress((void**)&ao, g_ao);

    dim3 gg(GM / BM, GN / BN);   // 32 x 8
    sgemm_kernel<0><<<gg, 256>>>(q, Wq, qh);
    sgemm_kernel<0><<<gg, 256>>>(k, Wk, kh);
    sgemm_kernel<0><<<gg, 256>>>(v, Wv, vh);

    cudaFuncSetAttribute(attn_kernel,
                         cudaFuncAttributeMaxDynamicSharedMemorySize,
                         ATTN_SMEM_BYTES);
    dim3 ga(SEQ / TQ, NHEAD, BATCH);   // 16 x 16 x 2
    attn_kernel<<<ga, 256, ATTN_SMEM_BYTES>>>(qh, kh, vh, mask, ao);

    sgemm_kernel<1><<<gg, 256>>>(ao, Wo, out);
}

// round 2
// speedup vs baseline: 1.4716x; 1.4716x over previous
#include <cuda_runtime.h>

// Problem constants
#define BATCH   2
#define SEQ     2048
#define DIMM    1024
#define NHEAD   16
#define HDIM    64

// ---------------- scratch (allocation-free: device globals) ----------------
static __device__ float g_qh[BATCH * NHEAD * SEQ * HDIM];
static __device__ float g_kh[BATCH * NHEAD * SEQ * HDIM];
static __device__ float g_vh[BATCH * NHEAD * SEQ * HDIM];
static __device__ float g_ao[BATCH * NHEAD * SEQ * HDIM];

// ---------------- tf32 helper ------------------------------------------------
__device__ __forceinline__ unsigned f2tf32(float x) {
    unsigned r;
    asm("cvt.rna.tf32.f32 %0, %1;" : "=r"(r) : "f"(x));
    return r;
}

// ---------------- tf32 MMA GEMM: 128x128 tile, BK=32, 8 warps ---------------
// MODE 0: projection  C_scatter[b,h,s,e] = A[4096,1024] * W(head-blocked [H,K,64])
// MODE 1: plain       C[4096,1024]       = A[4096,1024] * W[1024,1024]
#define GM 4096
#define GN 1024
#define GK 1024
#define BM 128
#define BN 128
#define BKK 32
#define SLD 136   // smem stride: 136 % 32 == 8 -> conflict-free frag loads

template <int MODE>
__global__ __launch_bounds__(256, 2)
void sgemm_tc_kernel(const float* __restrict__ A, const float* __restrict__ W,
                     float* __restrict__ C)
{
    __shared__ unsigned As[BKK][SLD];   // [k][m], tf32 bits
    __shared__ unsigned Bs[BKK][SLD];   // [k][n], tf32 bits

    const int tid  = threadIdx.x;
    const int m0   = blockIdx.x * BM;
    const int n0   = blockIdx.y * BN;
    const int warp = tid >> 5;
    const int lane = tid & 31;
    const int warpM = warp & 1;          // 2 warp-rows (64 rows each)
    const int warpN = warp >> 1;         // 4 warp-cols (32 cols each)
    const int g  = lane >> 2;            // groupID 0..7
    const int tq = lane & 3;             // 0..3

    // warp tile 64x32 = 4 m-frags x 4 n-frags of m16n8k8
    float acc[4][4][4];
#pragma unroll
    for (int i = 0; i < 4; i++)
#pragma unroll
        for (int j = 0; j < 4; j++)
#pragma unroll
            for (int r = 0; r < 4; r++) acc[i][j][r] = 0.f;

    for (int k0 = 0; k0 < GK; k0 += BKK) {
        // ---- A tile: 128 rows x 32 k -> As[k][m] (transposed), tf32 rna
#pragma unroll
        for (int p = 0; p < 4; p++) {
            int slot = tid + p * 256;          // 1024 float4 slots
            int row  = slot >> 3;              // 0..127
            int kq   = (slot & 7) * 4;         // 0..28
            float4 v = *(const float4*)(A + (size_t)(m0 + row) * GK + k0 + kq);
            As[kq + 0][row] = f2tf32(v.x);
            As[kq + 1][row] = f2tf32(v.y);
            As[kq + 2][row] = f2tf32(v.z);
            As[kq + 3][row] = f2tf32(v.w);
        }
        // ---- B tile: 32 k x 128 n -> Bs[k][n]
#pragma unroll
        for (int p = 0; p < 4; p++) {
            int slot = tid + p * 256;
            int kk   = slot >> 5;              // 0..31
            int c4   = (slot & 31) * 4;        // 0..124
            float4 v;
            if (MODE == 0) {
                int col = n0 + c4;
                int hh = col >> 6, e = col & 63;
                v = *(const float4*)(W + ((size_t)hh * GK + (k0 + kk)) * 64 + e);
            } else {
                v = *(const float4*)(W + (size_t)(k0 + kk) * GN + n0 + c4);
            }
            Bs[kk][c4 + 0] = f2tf32(v.x);
            Bs[kk][c4 + 1] = f2tf32(v.y);
            Bs[kk][c4 + 2] = f2tf32(v.z);
            Bs[kk][c4 + 3] = f2tf32(v.w);
        }
        __syncthreads();

        // ---- compute: 4 k-steps of 8
#pragma unroll
        for (int ks = 0; ks < 4; ks++) {
            const int kb = ks * 8;
            unsigned a[4][4], b[4][2];
#pragma unroll
            for (int mf = 0; mf < 4; mf++) {
                int m = warpM * 64 + mf * 16 + g;
                a[mf][0] = As[kb + tq][m];
                a[mf][1] = As[kb + tq][m + 8];
                a[mf][2] = As[kb + tq + 4][m];
                a[mf][3] = As[kb + tq + 4][m + 8];
            }
#pragma unroll
            for (int nf = 0; nf < 4; nf++) {
                int n = warpN * 32 + nf * 8 + g;
                b[nf][0] = Bs[kb + tq][n];
                b[nf][1] = Bs[kb + tq + 4][n];
            }
#pragma unroll
            for (int mf = 0; mf < 4; mf++)
#pragma unroll
                for (int nf = 0; nf < 4; nf++) {
                    asm volatile(
                        "mma.sync.aligned.m16n8k8.row.col.f32.tf32.tf32.f32 "
                        "{%0,%1,%2,%3}, {%4,%5,%6,%7}, {%8,%9}, {%0,%1,%2,%3};"
                        : "+f"(acc[mf][nf][0]), "+f"(acc[mf][nf][1]),
                          "+f"(acc[mf][nf][2]), "+f"(acc[mf][nf][3])
                        : "r"(a[mf][0]), "r"(a[mf][1]), "r"(a[mf][2]), "r"(a[mf][3]),
                          "r"(b[nf][0]), "r"(b[nf][1]));
                }
        }
        __syncthreads();
    }

    // ---- epilogue: c0,c1 -> (row, 2tq..2tq+1) ; c2,c3 -> (row+8, ...)
#pragma unroll
    for (int mf = 0; mf < 4; mf++) {
#pragma unroll
        for (int nf = 0; nf < 4; nf++) {
            const int gcol = n0 + warpN * 32 + nf * 8 + 2 * tq;
#pragma unroll
            for (int half = 0; half < 2; half++) {
                const int grow = m0 + warpM * 64 + mf * 16 + g + half * 8;
                const float2 val = make_float2(acc[mf][nf][half * 2],
                                               acc[mf][nf][half * 2 + 1]);
                if (MODE == 0) {
                    const int bb = grow >> 11, s = grow & 2047;
                    const int hh = gcol >> 6, e = gcol & 63;
                    *(float2*)(C + (((size_t)(bb * NHEAD + hh)) * SEQ + s) * HDIM + e) = val;
                } else {
                    *(float2*)(C + (size_t)grow * GN + gcol) = val;
                }
            }
        }
    }
}

// ---------------- Flash attention: TQ=128 rows / block, TK=64 ---------------
#define TQ 128
#define TK 64
#define LD 65

#define ATTN_SMEM_BYTES (((TQ + TK + TK + TQ) * LD) * 4 + (TK + TQ) * 4)

__global__ __launch_bounds__(256)
void attn_kernel(const float* __restrict__ QH, const float* __restrict__ KH,
                 const float* __restrict__ VH, const int* __restrict__ mask,
                 float* __restrict__ AO)
{
    extern __shared__ float sm[];
    float* Qs = sm;
    float* Ks = Qs + TQ * LD;
    float* Vs = Ks + TK * LD;
    float* Ps = Vs + TK * LD;
    int*   km = (int*)(Ps + TQ * LD);
    int*   qm = km + TK;

    const int b  = blockIdx.z;
    const int h  = blockIdx.y;
    const int q0 = blockIdx.x * TQ;
    const size_t base = ((size_t)(b * NHEAD + h)) * SEQ * HDIM;

    const int tid = threadIdx.x;
    const int tx = tid & 15;
    const int ty = tid >> 4;

    for (int idx = tid; idx < TQ * HDIM; idx += 256) {
        int r = idx >> 6, d = idx & 63;
        Qs[r * LD + d] = QH[base + (size_t)(q0 + r) * HDIM + d];
    }
    if (tid < TQ) qm[tid] = mask[b * SEQ + q0 + tid];

    const float NEGINF = __int_as_float(0xff800000u);
    float m[8], l[8], acc[8][4];
#pragma unroll
    for (int i = 0; i < 8; i++) {
        m[i] = NEGINF; l[i] = 0.f;
#pragma unroll
        for (int j = 0; j < 4; j++) acc[i][j] = 0.f;
    }

    const int ntiles = (q0 + TQ) / TK;
    for (int kt = 0; kt < ntiles; kt++) {
        const int t0 = kt * TK;
        __syncthreads();
        for (int idx = tid; idx < TK * HDIM; idx += 256) {
            int r = idx >> 6, d = idx & 63;
            Ks[r * LD + d] = KH[base + (size_t)(t0 + r) * HDIM + d];
            Vs[r * LD + d] = VH[base + (size_t)(t0 + r) * HDIM + d];
        }
        if (tid < TK) km[tid] = mask[b * SEQ + t0 + tid];
        __syncthreads();

        float sc[8][4];
#pragma unroll
        for (int i = 0; i < 8; i++)
#pragma unroll
            for (int j = 0; j < 4; j++) sc[i][j] = 0.f;

#pragma unroll 4
        for (int d = 0; d < HDIM; d++) {
            float qv[8], kv[4];
#pragma unroll
            for (int i = 0; i < 8; i++) qv[i] = Qs[(ty * 8 + i) * LD + d];
#pragma unroll
            for (int j = 0; j < 4; j++) kv[j] = Ks[(tx * 4 + j) * LD + d];
#pragma unroll
            for (int i = 0; i < 8; i++)
#pragma unroll
                for (int j = 0; j < 4; j++)
                    sc[i][j] = fmaf(qv[i], kv[j], sc[i][j]);
        }

#pragma unroll
        for (int i = 0; i < 8; i++) {
            const int r = ty * 8 + i;
            const int sg = q0 + r;
            const bool mr = (qm[r] != 0);
            float mx = NEGINF;
#pragma unroll
            for (int j = 0; j < 4; j++) {
                int t = t0 + tx * 4 + j;
                float val = (mr || (km[tx * 4 + j] != 0)) ? 0.f : sc[i][j] * 0.125f;
                if (t > sg) val = -1e30f;
                sc[i][j] = val;
                mx = fmaxf(mx, val);
            }
#pragma unroll
            for (int off = 8; off; off >>= 1)
                mx = fmaxf(mx, __shfl_xor_sync(0xffffffffu, mx, off));
            float mn = fmaxf(m[i], mx);
            float corr = __expf(m[i] - mn);
            float rs = 0.f;
#pragma unroll
            for (int j = 0; j < 4; j++) {
                float p = __expf(sc[i][j] - mn);
                sc[i][j] = p;
                rs += p;
            }
#pragma unroll
            for (int off = 8; off; off >>= 1)
                rs += __shfl_xor_sync(0xffffffffu, rs, off);
            l[i] = l[i] * corr + rs;
            m[i] = mn;
#pragma unroll
            for (int j = 0; j < 4; j++) acc[i][j] *= corr;
#pragma unroll
            for (int j = 0; j < 4; j++) Ps[r * LD + tx * 4 + j] = sc[i][j];
        }
        __syncwarp();

#pragma unroll 4
        for (int c = 0; c < TK; c++) {
            float vv[4];
#pragma unroll
            for (int j = 0; j < 4; j++) vv[j] = Vs[c * LD + tx * 4 + j];
#pragma unroll
            for (int i = 0; i < 8; i++) {
                float p = Ps[(ty * 8 + i) * LD + c];
#pragma unroll
                for (int j = 0; j < 4; j++)
                    acc[i][j] = fmaf(p, vv[j], acc[i][j]);
            }
        }
    }

#pragma unroll
    for (int i = 0; i < 8; i++) {
        const int r = ty * 8 + i;
        const float inv = 1.f / l[i];
#pragma unroll
        for (int j = 0; j < 4; j++)
            AO[base + (size_t)(q0 + r) * HDIM + tx * 4 + j] = acc[i][j] * inv;
    }
}

// ---------------- launch -----------------------------------------------------
extern "C" void kernel_launch(void* const* d_in, const int* in_sizes, int n_in,
                              void* d_out, int out_size)
{
    const float* q    = (const float*)d_in[0];
    const float* k    = (const float*)d_in[1];
    const float* v    = (const float*)d_in[2];
    const float* Wq   = (const float*)d_in[3];
    const float* Wk   = (const float*)d_in[4];
    const float* Wv   = (const float*)d_in[5];
    const float* Wo   = (const float*)d_in[6];
    const int*   mask = (const int*)d_in[7];
    float* out = (float*)d_out;

    float *qh, *kh, *vh, *ao;
    cudaGetSymbolAddress((void**)&qh, g_qh);
    cudaGetSymbolAddress((void**)&kh, g_kh);
    cudaGetSymbolAddress((void**)&vh, g_vh);
    cudaGetSymbolAddress((void**)&ao, g_ao);

    dim3 gg(GM / BM, GN / BN);   // 32 x 8
    sgemm_tc_kernel<0><<<gg, 256>>>(q, Wq, qh);
    sgemm_tc_kernel<0><<<gg, 256>>>(k, Wk, kh);
    sgemm_tc_kernel<0><<<gg, 256>>>(v, Wv, vh);

    cudaFuncSetAttribute(attn_kernel,
                         cudaFuncAttributeMaxDynamicSharedMemorySize,
                         ATTN_SMEM_BYTES);
    dim3 ga(SEQ / TQ, NHEAD, BATCH);   // 16 x 16 x 2
    attn_kernel<<<ga, 256, ATTN_SMEM_BYTES>>>(qh, kh, vh, mask, ao);

    sgemm_tc_kernel<1><<<gg, 256>>>(ao, Wo, out);
}

// round 3
// speedup vs baseline: 1.5545x; 1.0563x over previous
#include <cuda_runtime.h>

// Problem constants
#define BATCH   2
#define SEQ     2048
#define DIMM    1024
#define NHEAD   16
#define HDIM    64

// ---------------- scratch (allocation-free: device globals) ----------------
static __device__ float g_qh[BATCH * NHEAD * SEQ * HDIM];
static __device__ float g_kh[BATCH * NHEAD * SEQ * HDIM];
static __device__ float g_vh[BATCH * NHEAD * SEQ * HDIM];
static __device__ float g_ao[BATCH * NHEAD * SEQ * HDIM];

// ---------------- tf32 helper ------------------------------------------------
__device__ __forceinline__ unsigned f2tf32(float x) {
    unsigned r;
    asm("cvt.rna.tf32.f32 %0, %1;" : "=r"(r) : "f"(x));
    return r;
}

// ---------------- tf32 MMA GEMM: 128x128 tile, BK=32, 8 warps ---------------
// MODE 0: projection  C_scatter[b,h,s,e] = A[4096,1024] * W(head-blocked [H,K,64])
// MODE 1: plain       C[4096,1024]       = A[4096,1024] * W[1024,1024]
#define GM 4096
#define GN 1024
#define GK 1024
#define BM 128
#define BN 128
#define BKK 32
#define SLD 136   // smem stride: 136 % 32 == 8 -> conflict-free frag loads

template <int MODE>
__global__ __launch_bounds__(256, 2)
void sgemm_tc_kernel(const float* __restrict__ A, const float* __restrict__ W,
                     float* __restrict__ C)
{
    __shared__ unsigned As[BKK][SLD];   // [k][m], tf32 bits
    __shared__ unsigned Bs[BKK][SLD];   // [k][n], tf32 bits

    const int tid  = threadIdx.x;
    const int m0   = blockIdx.x * BM;
    const int n0   = blockIdx.y * BN;
    const int warp = tid >> 5;
    const int lane = tid & 31;
    const int warpM = warp & 1;          // 2 warp-rows (64 rows each)
    const int warpN = warp >> 1;         // 4 warp-cols (32 cols each)
    const int g  = lane >> 2;            // groupID 0..7
    const int tq = lane & 3;             // 0..3

    // warp tile 64x32 = 4 m-frags x 4 n-frags of m16n8k8
    float acc[4][4][4];
#pragma unroll
    for (int i = 0; i < 4; i++)
#pragma unroll
        for (int j = 0; j < 4; j++)
#pragma unroll
            for (int r = 0; r < 4; r++) acc[i][j][r] = 0.f;

    for (int k0 = 0; k0 < GK; k0 += BKK) {
        // ---- A tile: 128 rows x 32 k -> As[k][m] (transposed), tf32 rna
#pragma unroll
        for (int p = 0; p < 4; p++) {
            int slot = tid + p * 256;          // 1024 float4 slots
            int row  = slot >> 3;              // 0..127
            int kq   = (slot & 7) * 4;         // 0..28
            float4 v = *(const float4*)(A + (size_t)(m0 + row) * GK + k0 + kq);
            As[kq + 0][row] = f2tf32(v.x);
            As[kq + 1][row] = f2tf32(v.y);
            As[kq + 2][row] = f2tf32(v.z);
            As[kq + 3][row] = f2tf32(v.w);
        }
        // ---- B tile: 32 k x 128 n -> Bs[k][n]
#pragma unroll
        for (int p = 0; p < 4; p++) {
            int slot = tid + p * 256;
            int kk   = slot >> 5;              // 0..31
            int c4   = (slot & 31) * 4;        // 0..124
            float4 v;
            if (MODE == 0) {
                int col = n0 + c4;
                int hh = col >> 6, e = col & 63;
                v = *(const float4*)(W + ((size_t)hh * GK + (k0 + kk)) * 64 + e);
            } else {
                v = *(const float4*)(W + (size_t)(k0 + kk) * GN + n0 + c4);
            }
            Bs[kk][c4 + 0] = f2tf32(v.x);
            Bs[kk][c4 + 1] = f2tf32(v.y);
            Bs[kk][c4 + 2] = f2tf32(v.z);
            Bs[kk][c4 + 3] = f2tf32(v.w);
        }
        __syncthreads();

        // ---- compute: 4 k-steps of 8
#pragma unroll
        for (int ks = 0; ks < 4; ks++) {
            const int kb = ks * 8;
            unsigned a[4][4], b[4][2];
#pragma unroll
            for (int mf = 0; mf < 4; mf++) {
                int m = warpM * 64 + mf * 16 + g;
                a[mf][0] = As[kb + tq][m];
                a[mf][1] = As[kb + tq][m + 8];
                a[mf][2] = As[kb + tq + 4][m];
                a[mf][3] = As[kb + tq + 4][m + 8];
            }
#pragma unroll
            for (int nf = 0; nf < 4; nf++) {
                int n = warpN * 32 + nf * 8 + g;
                b[nf][0] = Bs[kb + tq][n];
                b[nf][1] = Bs[kb + tq + 4][n];
            }
#pragma unroll
            for (int mf = 0; mf < 4; mf++)
#pragma unroll
                for (int nf = 0; nf < 4; nf++) {
                    asm volatile(
                        "mma.sync.aligned.m16n8k8.row.col.f32.tf32.tf32.f32 "
                        "{%0,%1,%2,%3}, {%4,%5,%6,%7}, {%8,%9}, {%0,%1,%2,%3};"
                        : "+f"(acc[mf][nf][0]), "+f"(acc[mf][nf][1]),
                          "+f"(acc[mf][nf][2]), "+f"(acc[mf][nf][3])
                        : "r"(a[mf][0]), "r"(a[mf][1]), "r"(a[mf][2]), "r"(a[mf][3]),
                          "r"(b[nf][0]), "r"(b[nf][1]));
                }
        }
        __syncthreads();
    }

    // ---- epilogue
#pragma unroll
    for (int mf = 0; mf < 4; mf++) {
#pragma unroll
        for (int nf = 0; nf < 4; nf++) {
            const int gcol = n0 + warpN * 32 + nf * 8 + 2 * tq;
#pragma unroll
            for (int half = 0; half < 2; half++) {
                const int grow = m0 + warpM * 64 + mf * 16 + g + half * 8;
                const float2 val = make_float2(acc[mf][nf][half * 2],
                                               acc[mf][nf][half * 2 + 1]);
                if (MODE == 0) {
                    const int bb = grow >> 11, s = grow & 2047;
                    const int hh = gcol >> 6, e = gcol & 63;
                    *(float2*)(C + (((size_t)(bb * NHEAD + hh)) * SEQ + s) * HDIM + e) = val;
                } else {
                    *(float2*)(C + (size_t)grow * GN + gcol) = val;
                }
            }
        }
    }
}

// ---------------- Flash attention: TQ=128, TK=64, 512 threads ---------------
// Thread (tx, ty): tx = tid&15 owns cols {tx+16j}, ty = tid>>4 owns rows {ty*4+i}
// Smem stride 68: float4 loads, conflict-free by construction.
#define TQ 128
#define TK 64
#define ALD 68

#define ATTN_SMEM_BYTES ((TQ * ALD + 3 * TK * ALD + TQ * ALD) * 4 + (TK + TQ) * 4)

__global__ __launch_bounds__(512, 1)
void attn_kernel(const float* __restrict__ QH, const float* __restrict__ KH,
                 const float* __restrict__ VH, const int* __restrict__ mask,
                 float* __restrict__ AO)
{
    extern __shared__ float sm[];
    float* Qs = sm;                       // [128][68], pre-scaled by 1/8
    float* Ks = Qs + TQ * ALD;            // [64][68]
    float* Vs = Ks + TK * ALD;            // [64][68]  (staging, row-major)
    float* Vt = Vs + TK * ALD;            // [64][68]  (transposed: [d][c])
    float* Ps = Vt + TK * ALD;            // [128][68]
    int*   km = (int*)(Ps + TQ * ALD);
    int*   qm = km + TK;

    const int b  = blockIdx.z;
    const int h  = blockIdx.y;
    const int q0 = blockIdx.x * TQ;
    const size_t base = ((size_t)(b * NHEAD + h)) * SEQ * HDIM;

    const int tid = threadIdx.x;
    const int tx = tid & 15;     // column group
    const int ty = tid >> 4;     // row group (0..31), rows ty*4+i

    // Load Q tile (pre-scaled) + row masks
#pragma unroll
    for (int p = 0; p < 4; p++) {
        int slot = tid + p * 512;            // 2048 float4 slots
        int r  = slot >> 4;
        int d4 = (slot & 15) * 4;
        float4 v = *(const float4*)(QH + base + (size_t)(q0 + r) * HDIM + d4);
        v.x *= 0.125f; v.y *= 0.125f; v.z *= 0.125f; v.w *= 0.125f;
        *(float4*)&Qs[r * ALD + d4] = v;
    }
    if (tid < TQ) qm[tid] = mask[b * SEQ + q0 + tid];

    const float NEGINF = __int_as_float(0xff800000u);
    float m[4], l[4], acc[4][4];
#pragma unroll
    for (int i = 0; i < 4; i++) {
        m[i] = NEGINF; l[i] = 0.f;
#pragma unroll
        for (int j = 0; j < 4; j++) acc[i][j] = 0.f;
    }

    const int ntiles = (q0 + TQ) / TK;
    for (int kt = 0; kt < ntiles; kt++) {
        const int t0 = kt * TK;
        __syncthreads();   // prev iter's Ks/Vs/Vt/Ps reads done (also Qs/qm on kt=0)

        // Load K, V tiles (coalesced float4)
#pragma unroll
        for (int p = 0; p < 2; p++) {
            int slot = tid + p * 512;          // 1024 float4 slots
            int r  = slot >> 4;
            int d4 = (slot & 15) * 4;
            *(float4*)&Ks[r * ALD + d4] =
                *(const float4*)(KH + base + (size_t)(t0 + r) * HDIM + d4);
            *(float4*)&Vs[r * ALD + d4] =
                *(const float4*)(VH + base + (size_t)(t0 + r) * HDIM + d4);
        }
        if (tid < TK) km[tid] = mask[b * SEQ + t0 + tid];
        __syncthreads();

        // ---- QK: sc[i][j] = Qrow(ty*4+i) . Krow(tx+16j)  (Q pre-scaled)
        float sc[4][4];
#pragma unroll
        for (int i = 0; i < 4; i++)
#pragma unroll
            for (int j = 0; j < 4; j++) sc[i][j] = 0.f;

#pragma unroll
        for (int d4 = 0; d4 < HDIM; d4 += 4) {
            float4 qv[4];
#pragma unroll
            for (int i = 0; i < 4; i++)
                qv[i] = *(const float4*)&Qs[(ty * 4 + i) * ALD + d4];
#pragma unroll
            for (int j = 0; j < 4; j++) {
                float4 kv = *(const float4*)&Ks[(tx + 16 * j) * ALD + d4];
#pragma unroll
                for (int i = 0; i < 4; i++) {
                    sc[i][j] = fmaf(qv[i].x, kv.x, sc[i][j]);
                    sc[i][j] = fmaf(qv[i].y, kv.y, sc[i][j]);
                    sc[i][j] = fmaf(qv[i].z, kv.z, sc[i][j]);
                    sc[i][j] = fmaf(qv[i].w, kv.w, sc[i][j]);
                }
            }
        }

        // ---- transpose Vs[c][d] -> Vt[d][c]
#pragma unroll
        for (int p = 0; p < 2; p++) {
            int slot = tid + p * 512;          // 1024 float4 slots
            int c  = slot & 63;
            int d4 = (slot >> 6) * 4;
            float4 v = *(const float4*)&Vs[c * ALD + d4];
            Vt[(d4 + 0) * ALD + c] = v.x;
            Vt[(d4 + 1) * ALD + c] = v.y;
            Vt[(d4 + 2) * ALD + c] = v.z;
            Vt[(d4 + 3) * ALD + c] = v.w;
        }

        // ---- mask + online softmax, write P
#pragma unroll
        for (int i = 0; i < 4; i++) {
            const int r  = ty * 4 + i;
            const int sg = q0 + r;
            const bool mr = (qm[r] != 0);
            float mx = NEGINF;
#pragma unroll
            for (int j = 0; j < 4; j++) {
                int t = t0 + tx + 16 * j;
                float val = (mr || (km[tx + 16 * j] != 0)) ? 0.f : sc[i][j];
                if (t > sg) val = -1e30f;
                sc[i][j] = val;
                mx = fmaxf(mx, val);
            }
#pragma unroll
            for (int off = 8; off; off >>= 1)
                mx = fmaxf(mx, __shfl_xor_sync(0xffffffffu, mx, off));
            float mn = fmaxf(m[i], mx);
            float corr = __expf(m[i] - mn);
            float rs = 0.f;
#pragma unroll
            for (int j = 0; j < 4; j++) {
                float p = __expf(sc[i][j] - mn);
                sc[i][j] = p;
                rs += p;
            }
#pragma unroll
            for (int off = 8; off; off >>= 1)
                rs += __shfl_xor_sync(0xffffffffu, rs, off);
            l[i] = l[i] * corr + rs;
            m[i] = mn;
#pragma unroll
            for (int j = 0; j < 4; j++) acc[i][j] *= corr;
#pragma unroll
            for (int j = 0; j < 4; j++) Ps[r * ALD + tx + 16 * j] = sc[i][j];
        }
        __syncthreads();   // Vt + Ps ready for all

        // ---- PV: acc[i][j] += sum_c P[row][c] * Vt[col][c]
#pragma unroll
        for (int c4 = 0; c4 < TK; c4 += 4) {
            float4 p4[4];
#pragma unroll
            for (int i = 0; i < 4; i++)
                p4[i] = *(const float4*)&Ps[(ty * 4 + i) * ALD + c4];
#pragma unroll
            for (int j = 0; j < 4; j++) {
                float4 vt = *(const float4*)&Vt[(tx + 16 * j) * ALD + c4];
#pragma unroll
                for (int i = 0; i < 4; i++) {
                    acc[i][j] = fmaf(p4[i].x, vt.x, acc[i][j]);
                    acc[i][j] = fmaf(p4[i].y, vt.y, acc[i][j]);
                    acc[i][j] = fmaf(p4[i].z, vt.z, acc[i][j]);
                    acc[i][j] = fmaf(p4[i].w, vt.w, acc[i][j]);
                }
            }
        }
    }

    // epilogue: normalize and store [B,H,S,hd]
#pragma unroll
    for (int i = 0; i < 4; i++) {
        const int r = ty * 4 + i;
        const float inv = 1.f / l[i];
#pragma unroll
        for (int j = 0; j < 4; j++)
            AO[base + (size_t)(q0 + r) * HDIM + tx + 16 * j] = acc[i][j] * inv;
    }
}

// ---------------- launch -----------------------------------------------------
extern "C" void kernel_launch(void* const* d_in, const int* in_sizes, int n_in,
                              void* d_out, int out_size)
{
    const float* q    = (const float*)d_in[0];
    const float* k    = (const float*)d_in[1];
    const float* v    = (const float*)d_in[2];
    const float* Wq   = (const float*)d_in[3];
    const float* Wk   = (const float*)d_in[4];
    const float* Wv   = (const float*)d_in[5];
    const float* Wo   = (const float*)d_in[6];
    const int*   mask = (const int*)d_in[7];
    float* out = (float*)d_out;

    float *qh, *kh, *vh, *ao;
    cudaGetSymbolAddress((void**)&qh, g_qh);
    cudaGetSymbolAddress((void**)&kh, g_kh);
    cudaGetSymbolAddress((void**)&vh, g_vh);
    cudaGetSymbolAddress((void**)&ao, g_ao);

    dim3 gg(GM / BM, GN / BN);   // 32 x 8
    sgemm_tc_kernel<0><<<gg, 256>>>(q, Wq, qh);
    sgemm_tc_kernel<0><<<gg, 256>>>(k, Wk, kh);
    sgemm_tc_kernel<0><<<gg, 256>>>(v, Wv, vh);

    cudaFuncSetAttribute(attn_kernel,
                         cudaFuncAttributeMaxDynamicSharedMemorySize,
                         ATTN_SMEM_BYTES);
    dim3 ga(SEQ / TQ, NHEAD, BATCH);   // 16 x 16 x 2
    attn_kernel<<<ga, 512, ATTN_SMEM_BYTES>>>(qh, kh, vh, mask, ao);

    sgemm_tc_kernel<1><<<gg, 256>>>(ao, Wo, out);
}

// round 4
// speedup vs baseline: 2.9168x; 1.8764x over previous
#include <cuda_runtime.h>
#include <cuda_fp16.h>
#include <cstdint>

// Problem constants
#define BATCH   2
#define SEQ     2048
#define DIMM    1024
#define NHEAD   16
#define HDIM    64

// ---------------- scratch (allocation-free: device globals) ----------------
static __device__ float g_qh[BATCH * NHEAD * SEQ * HDIM];
static __device__ float g_kh[BATCH * NHEAD * SEQ * HDIM];
static __device__ float g_vh[BATCH * NHEAD * SEQ * HDIM];
static __device__ float g_ao[BATCH * NHEAD * SEQ * HDIM];

// ---------------- tf32 helper ------------------------------------------------
__device__ __forceinline__ unsigned f2tf32(float x) {
    unsigned r;
    asm("cvt.rna.tf32.f32 %0, %1;" : "=r"(r) : "f"(x));
    return r;
}

// ---------------- tf32 MMA GEMM: 128x128 tile, BK=32, 8 warps ---------------
#define GM 4096
#define GN 1024
#define GK 1024
#define BM 128
#define BN 128
#define BKK 32
#define SLD 136

template <int MODE>
__global__ __launch_bounds__(256, 2)
void sgemm_tc_kernel(const float* __restrict__ A, const float* __restrict__ W,
                     float* __restrict__ C)
{
    __shared__ unsigned As[BKK][SLD];
    __shared__ unsigned Bs[BKK][SLD];

    const int tid  = threadIdx.x;
    const int m0   = blockIdx.x * BM;
    const int n0   = blockIdx.y * BN;
    const int warp = tid >> 5;
    const int lane = tid & 31;
    const int warpM = warp & 1;
    const int warpN = warp >> 1;
    const int g  = lane >> 2;
    const int tq = lane & 3;

    float acc[4][4][4];
#pragma unroll
    for (int i = 0; i < 4; i++)
#pragma unroll
        for (int j = 0; j < 4; j++)
#pragma unroll
            for (int r = 0; r < 4; r++) acc[i][j][r] = 0.f;

    for (int k0 = 0; k0 < GK; k0 += BKK) {
#pragma unroll
        for (int p = 0; p < 4; p++) {
            int slot = tid + p * 256;
            int row  = slot >> 3;
            int kq   = (slot & 7) * 4;
            float4 v = *(const float4*)(A + (size_t)(m0 + row) * GK + k0 + kq);
            As[kq + 0][row] = f2tf32(v.x);
            As[kq + 1][row] = f2tf32(v.y);
            As[kq + 2][row] = f2tf32(v.z);
            As[kq + 3][row] = f2tf32(v.w);
        }
#pragma unroll
        for (int p = 0; p < 4; p++) {
            int slot = tid + p * 256;
            int kk   = slot >> 5;
            int c4   = (slot & 31) * 4;
            float4 v;
            if (MODE == 0) {
                int col = n0 + c4;
                int hh = col >> 6, e = col & 63;
                v = *(const float4*)(W + ((size_t)hh * GK + (k0 + kk)) * 64 + e);
            } else {
                v = *(const float4*)(W + (size_t)(k0 + kk) * GN + n0 + c4);
            }
            Bs[kk][c4 + 0] = f2tf32(v.x);
            Bs[kk][c4 + 1] = f2tf32(v.y);
            Bs[kk][c4 + 2] = f2tf32(v.z);
            Bs[kk][c4 + 3] = f2tf32(v.w);
        }
        __syncthreads();

#pragma unroll
        for (int ks = 0; ks < 4; ks++) {
            const int kb = ks * 8;
            unsigned a[4][4], b[4][2];
#pragma unroll
            for (int mf = 0; mf < 4; mf++) {
                int m = warpM * 64 + mf * 16 + g;
                a[mf][0] = As[kb + tq][m];
                a[mf][1] = As[kb + tq][m + 8];
                a[mf][2] = As[kb + tq + 4][m];
                a[mf][3] = As[kb + tq + 4][m + 8];
            }
#pragma unroll
            for (int nf = 0; nf < 4; nf++) {
                int n = warpN * 32 + nf * 8 + g;
                b[nf][0] = Bs[kb + tq][n];
                b[nf][1] = Bs[kb + tq + 4][n];
            }
#pragma unroll
            for (int mf = 0; mf < 4; mf++)
#pragma unroll
                for (int nf = 0; nf < 4; nf++) {
                    asm volatile(
                        "mma.sync.aligned.m16n8k8.row.col.f32.tf32.tf32.f32 "
                        "{%0,%1,%2,%3}, {%4,%5,%6,%7}, {%8,%9}, {%0,%1,%2,%3};"
                        : "+f"(acc[mf][nf][0]), "+f"(acc[mf][nf][1]),
                          "+f"(acc[mf][nf][2]), "+f"(acc[mf][nf][3])
                        : "r"(a[mf][0]), "r"(a[mf][1]), "r"(a[mf][2]), "r"(a[mf][3]),
                          "r"(b[nf][0]), "r"(b[nf][1]));
                }
        }
        __syncthreads();
    }

#pragma unroll
    for (int mf = 0; mf < 4; mf++) {
#pragma unroll
        for (int nf = 0; nf < 4; nf++) {
            const int gcol = n0 + warpN * 32 + nf * 8 + 2 * tq;
#pragma unroll
            for (int half = 0; half < 2; half++) {
                const int grow = m0 + warpM * 64 + mf * 16 + g + half * 8;
                const float2 val = make_float2(acc[mf][nf][half * 2],
                                               acc[mf][nf][half * 2 + 1]);
                if (MODE == 0) {
                    const int bb = grow >> 11, s = grow & 2047;
                    const int hh = gcol >> 6, e = gcol & 63;
                    *(float2*)(C + (((size_t)(bb * NHEAD + hh)) * SEQ + s) * HDIM + e) = val;
                } else {
                    *(float2*)(C + (size_t)grow * GN + gcol) = val;
                }
            }
        }
    }
}

// ================= MMA flash attention ======================================
// 256 threads = 8 warps; warp w owns q-rows [w*16, w*16+16) of a TQ=128 tile.
// QK: fp16 2-term split (3 mma), PV: single fp16, fp32 accum everywhere.
#define TQA 128
#define TKA 64
#define HST 72          // half stride (bytes 144): conflict-free frag loads

#define ATTN_SMEM ((128 + 128 + 64 + 64 + 64) * HST * 2 + (128 + 64) * 4)

#define MMA16816(CC, A0, A1, A2, A3, B0, B1)                                  \
    asm volatile(                                                             \
        "mma.sync.aligned.m16n8k16.row.col.f32.f16.f16.f32 "                  \
        "{%0,%1,%2,%3}, {%4,%5,%6,%7}, {%8,%9}, {%0,%1,%2,%3};"               \
        : "+f"((CC)[0]), "+f"((CC)[1]), "+f"((CC)[2]), "+f"((CC)[3])          \
        : "r"(A0), "r"(A1), "r"(A2), "r"(A3), "r"(B0), "r"(B1))

__device__ __forceinline__ uint32_t pack_h2(float a, float b) {
    __half2 h = __floats2half2_rn(a, b);
    return *(uint32_t*)&h;
}

// split (x,y) into fp16 hi/lo pairs and store as half2 words
__device__ __forceinline__ void split_store(__half* hip, __half* lop,
                                            float x, float y) {
    __half hx = __float2half_rn(x), hy = __float2half_rn(y);
    float  rx = x - __half2float(hx), ry = y - __half2float(hy);
    *(uint32_t*)hip = pack_h2(__half2float(hx), __half2float(hy));
    *(uint32_t*)lop = pack_h2(rx, ry);
}

__global__ __launch_bounds__(256, 2)
void attn_mma_kernel(const float* __restrict__ QH, const float* __restrict__ KH,
                     const float* __restrict__ VH, const int* __restrict__ mask,
                     float* __restrict__ AO)
{
    extern __shared__ char smem_raw[];
    __half* Qhi = (__half*)smem_raw;
    __half* Qlo = Qhi + 128 * HST;
    __half* Khi = Qlo + 128 * HST;
    __half* Klo = Khi + 64 * HST;
    __half* Vs  = Klo + 64 * HST;     // [c][d] fp16
    int*    qm  = (int*)(Vs + 64 * HST);
    int*    km  = qm + 128;

    const int b = blockIdx.z, h = blockIdx.y;
    const int qt = (int)gridDim.x - 1 - (int)blockIdx.x;   // heavy tiles first
    const int q0 = qt * TQA;
    const size_t base = ((size_t)(b * NHEAD + h)) * SEQ * HDIM;

    const int tid  = threadIdx.x;
    const int warp = tid >> 5, lane = tid & 31;
    const int g = lane >> 2, t = lane & 3;

    // ---- load Q tile: scale 1/8, split to fp16 hi/lo
#pragma unroll
    for (int p = 0; p < 8; p++) {
        int slot = tid + p * 256;              // 2048 float4 slots
        int r  = slot >> 4;
        int d4 = (slot & 15) * 4;
        float4 v = *(const float4*)(QH + base + (size_t)(q0 + r) * HDIM + d4);
        v.x *= 0.125f; v.y *= 0.125f; v.z *= 0.125f; v.w *= 0.125f;
        split_store(&Qhi[r * HST + d4],     &Qlo[r * HST + d4],     v.x, v.y);
        split_store(&Qhi[r * HST + d4 + 2], &Qlo[r * HST + d4 + 2], v.z, v.w);
    }
    if (tid < 128) qm[tid] = mask[b * SEQ + q0 + tid];

    const int r0l = warp * 16 + g;       // local rows this thread owns
    const int r1l = r0l + 8;
    const int srow0 = q0 + r0l, srow1 = q0 + r1l;

    const float NEGINF = __int_as_float(0xff800000u);
    float m0 = NEGINF, m1 = NEGINF, l0 = 0.f, l1 = 0.f;
    float acc[8][4];
#pragma unroll
    for (int i = 0; i < 8; i++)
#pragma unroll
        for (int j = 0; j < 4; j++) acc[i][j] = 0.f;

    // per-lane base address for ldmatrix on Vs (lanes 0-15 supply rows)
    uint32_t vbase = (uint32_t)__cvta_generic_to_shared(Vs) +
                     (uint32_t)(lane & 15) * (HST * 2);

    const int ntiles = (q0 + TQA) / TKA;
    for (int kt = 0; kt < ntiles; kt++) {
        const int t0 = kt * TKA;
        __syncthreads();    // prior-iteration reads done (and Q/qm on kt=0)

        // ---- load K (split) and V (single fp16), coalesced float4
#pragma unroll
        for (int p = 0; p < 4; p++) {
            int slot = tid + p * 256;          // 1024 slots
            int r  = slot >> 4;
            int d4 = (slot & 15) * 4;
            float4 kv = *(const float4*)(KH + base + (size_t)(t0 + r) * HDIM + d4);
            split_store(&Khi[r * HST + d4],     &Klo[r * HST + d4],     kv.x, kv.y);
            split_store(&Khi[r * HST + d4 + 2], &Klo[r * HST + d4 + 2], kv.z, kv.w);
            float4 vv = *(const float4*)(VH + base + (size_t)(t0 + r) * HDIM + d4);
            *(uint32_t*)&Vs[r * HST + d4]     = pack_h2(vv.x, vv.y);
            *(uint32_t*)&Vs[r * HST + d4 + 2] = pack_h2(vv.z, vv.w);
        }
        if (tid < 64) km[tid] = mask[b * SEQ + t0 + tid];
        __syncthreads();

        // ---- QK: sc[nf] covers cols nf*8 + {2t,2t+1}, rows {g, g+8}
        float sc[8][4];
#pragma unroll
        for (int i = 0; i < 8; i++)
#pragma unroll
            for (int j = 0; j < 4; j++) sc[i][j] = 0.f;

#pragma unroll
        for (int kj = 0; kj < 4; kj++) {
            const int koff = kj * 16 + 2 * t;
            uint32_t ah0 = *(const uint32_t*)&Qhi[r0l * HST + koff];
            uint32_t ah1 = *(const uint32_t*)&Qhi[r1l * HST + koff];
            uint32_t ah2 = *(const uint32_t*)&Qhi[r0l * HST + koff + 8];
            uint32_t ah3 = *(const uint32_t*)&Qhi[r1l * HST + koff + 8];
            uint32_t al0 = *(const uint32_t*)&Qlo[r0l * HST + koff];
            uint32_t al1 = *(const uint32_t*)&Qlo[r1l * HST + koff];
            uint32_t al2 = *(const uint32_t*)&Qlo[r0l * HST + koff + 8];
            uint32_t al3 = *(const uint32_t*)&Qlo[r1l * HST + koff + 8];
#pragma unroll
            for (int nf = 0; nf < 8; nf++) {
                const int krow = nf * 8 + g;
                uint32_t bh0 = *(const uint32_t*)&Khi[krow * HST + koff];
                uint32_t bh1 = *(const uint32_t*)&Khi[krow * HST + koff + 8];
                uint32_t bl0 = *(const uint32_t*)&Klo[krow * HST + koff];
                uint32_t bl1 = *(const uint32_t*)&Klo[krow * HST + koff + 8];
                MMA16816(sc[nf], ah0, ah1, ah2, ah3, bh0, bh1);  // hi*hi
                MMA16816(sc[nf], ah0, ah1, ah2, ah3, bl0, bl1);  // hi*lo
                MMA16816(sc[nf], al0, al1, al2, al3, bh0, bh1);  // lo*hi
            }
        }

        // ---- mask + online softmax (warp-local: rows live in this warp)
        const bool rm0 = (qm[r0l] != 0), rm1 = (qm[r1l] != 0);
        float mx0 = m0, mx1 = m1;
#pragma unroll
        for (int nf = 0; nf < 8; nf++) {
            const int c0i = nf * 8 + 2 * t, c1i = c0i + 1;
            const bool cm0 = (km[c0i] != 0), cm1 = (km[c1i] != 0);
            const int tc0 = t0 + c0i, tc1 = t0 + c1i;
            float v00 = (rm0 | cm0) ? 0.f : sc[nf][0]; if (tc0 > srow0) v00 = -1e30f;
            float v01 = (rm0 | cm1) ? 0.f : sc[nf][1]; if (tc1 > srow0) v01 = -1e30f;
            float v10 = (rm1 | cm0) ? 0.f : sc[nf][2]; if (tc0 > srow1) v10 = -1e30f;
            float v11 = (rm1 | cm1) ? 0.f : sc[nf][3]; if (tc1 > srow1) v11 = -1e30f;
            sc[nf][0] = v00; sc[nf][1] = v01; sc[nf][2] = v10; sc[nf][3] = v11;
            mx0 = fmaxf(mx0, fmaxf(v00, v01));
            mx1 = fmaxf(mx1, fmaxf(v10, v11));
        }
#pragma unroll
        for (int off = 1; off <= 2; off <<= 1) {
            mx0 = fmaxf(mx0, __shfl_xor_sync(0xffffffffu, mx0, off));
            mx1 = fmaxf(mx1, __shfl_xor_sync(0xffffffffu, mx1, off));
        }
        const float corr0 = __expf(m0 - mx0);
        const float corr1 = __expf(m1 - mx1);
        float rs0 = 0.f, rs1 = 0.f;
#pragma unroll
        for (int nf = 0; nf < 8; nf++) {
            float p00 = __expf(sc[nf][0] - mx0);
            float p01 = __expf(sc[nf][1] - mx0);
            float p10 = __expf(sc[nf][2] - mx1);
            float p11 = __expf(sc[nf][3] - mx1);
            sc[nf][0] = p00; sc[nf][1] = p01; sc[nf][2] = p10; sc[nf][3] = p11;
            rs0 += p00 + p01;
            rs1 += p10 + p11;
        }
#pragma unroll
        for (int off = 1; off <= 2; off <<= 1) {
            rs0 += __shfl_xor_sync(0xffffffffu, rs0, off);
            rs1 += __shfl_xor_sync(0xffffffffu, rs1, off);
        }
        l0 = l0 * corr0 + rs0;  m0 = mx0;
        l1 = l1 * corr1 + rs1;  m1 = mx1;
#pragma unroll
        for (int nfd = 0; nfd < 8; nfd++) {
            acc[nfd][0] *= corr0; acc[nfd][1] *= corr0;
            acc[nfd][2] *= corr1; acc[nfd][3] *= corr1;
        }

        // ---- PV: P fragments re-packed from sc (C-frag -> A-frag identity)
#pragma unroll
        for (int kj = 0; kj < 4; kj++) {
            uint32_t a0 = pack_h2(sc[2 * kj][0],     sc[2 * kj][1]);
            uint32_t a1 = pack_h2(sc[2 * kj][2],     sc[2 * kj][3]);
            uint32_t a2 = pack_h2(sc[2 * kj + 1][0], sc[2 * kj + 1][1]);
            uint32_t a3 = pack_h2(sc[2 * kj + 1][2], sc[2 * kj + 1][3]);
            const uint32_t vrow = vbase + (uint32_t)kj * 16 * (HST * 2);
#pragma unroll
            for (int nfd = 0; nfd < 8; nfd++) {
                uint32_t b0, b1;
                asm volatile(
                    "ldmatrix.sync.aligned.m8n8.x2.trans.shared.b16 {%0,%1}, [%2];"
                    : "=r"(b0), "=r"(b1)
                    : "r"(vrow + (uint32_t)nfd * 16));
                MMA16816(acc[nfd], a0, a1, a2, a3, b0, b1);
            }
        }
    }

    // ---- epilogue: normalize, store [B,H,S,hd]
    const float inv0 = 1.f / l0, inv1 = 1.f / l1;
#pragma unroll
    for (int nfd = 0; nfd < 8; nfd++) {
        const int dcol = nfd * 8 + 2 * t;
        *(float2*)(AO + base + (size_t)srow0 * HDIM + dcol) =
            make_float2(acc[nfd][0] * inv0, acc[nfd][1] * inv0);
        *(float2*)(AO + base + (size_t)srow1 * HDIM + dcol) =
            make_float2(acc[nfd][2] * inv1, acc[nfd][3] * inv1);
    }
}

// ---------------- launch -----------------------------------------------------
extern "C" void kernel_launch(void* const* d_in, const int* in_sizes, int n_in,
                              void* d_out, int out_size)
{
    const float* q    = (const float*)d_in[0];
    const float* k    = (const float*)d_in[1];
    const float* v    = (const float*)d_in[2];
    const float* Wq   = (const float*)d_in[3];
    const float* Wk   = (const float*)d_in[4];
    const float* Wv   = (const float*)d_in[5];
    const float* Wo   = (const float*)d_in[6];
    const int*   mask = (const int*)d_in[7];
    float* out = (float*)d_out;

    float *qh, *kh, *vh, *ao;
    cudaGetSymbolAddress((void**)&qh, g_qh);
    cudaGetSymbolAddress((void**)&kh, g_kh);
    cudaGetSymbolAddress((void**)&vh, g_vh);
    cudaGetSymbolAddress((void**)&ao, g_ao);

    dim3 gg(GM / BM, GN / BN);   // 32 x 8
    sgemm_tc_kernel<0><<<gg, 256>>>(q, Wq, qh);
    sgemm_tc_kernel<0><<<gg, 256>>>(k, Wk, kh);
    sgemm_tc_kernel<0><<<gg, 256>>>(v, Wv, vh);

    cudaFuncSetAttribute(attn_mma_kernel,
                         cudaFuncAttributeMaxDynamicSharedMemorySize,
                         ATTN_SMEM);
    dim3 ga(SEQ / TQA, NHEAD, BATCH);   // 16 x 16 x 2
    attn_mma_kernel<<<ga, 256, ATTN_SMEM>>>(qh, kh, vh, mask, ao);

    sgemm_tc_kernel<1><<<gg, 256>>>(ao, Wo, out);
}

// round 5
// speedup vs baseline: 3.6111x; 1.2380x over previous
#include <cuda_runtime.h>
#include <cuda_fp16.h>
#include <cstdint>

// Problem constants
#define BATCH   2
#define SEQ     2048
#define DIMM    1024
#define NHEAD   16
#define HDIM    64

// ---------------- scratch (allocation-free: device globals) ----------------
static __device__ float    g_qh[BATCH * NHEAD * SEQ * HDIM];
static __device__ float    g_kh[BATCH * NHEAD * SEQ * HDIM];
static __device__ float    g_vh[BATCH * NHEAD * SEQ * HDIM];
static __device__ float    g_ao[BATCH * NHEAD * SEQ * HDIM];   // tf32 bits
static __device__ unsigned g_qt[BATCH * SEQ * DIMM];           // tf32 inputs
static __device__ unsigned g_kt[BATCH * SEQ * DIMM];
static __device__ unsigned g_vt[BATCH * SEQ * DIMM];
static __device__ unsigned g_wq[NHEAD * DIMM * HDIM];          // tf32 weights
static __device__ unsigned g_wk[NHEAD * DIMM * HDIM];
static __device__ unsigned g_wv[NHEAD * DIMM * HDIM];
static __device__ unsigned g_wo[DIMM * DIMM];

// ---------------- tf32 helpers ----------------------------------------------
__device__ __forceinline__ unsigned f2tf32(float x) {
    unsigned r;
    asm("cvt.rna.tf32.f32 %0, %1;" : "=r"(r) : "f"(x));
    return r;
}

__device__ __forceinline__ void cp16(void* smem_dst, const void* gmem_src) {
    uint32_t s = (uint32_t)__cvta_generic_to_shared(smem_dst);
    asm volatile("cp.async.cg.shared.global [%0], [%1], 16;"
                 :: "r"(s), "l"(gmem_src));
}

// ---------------- preconvert kernels -----------------------------------------
__global__ __launch_bounds__(256)
void cvtqkv_kernel(const float* __restrict__ q, const float* __restrict__ k,
                   const float* __restrict__ v,
                   unsigned* __restrict__ oq, unsigned* __restrict__ ok,
                   unsigned* __restrict__ ov)
{
    const float* s = (blockIdx.y == 0) ? q : (blockIdx.y == 1) ? k : v;
    unsigned*    d = (blockIdx.y == 0) ? oq : (blockIdx.y == 1) ? ok : ov;
    size_t i = ((size_t)blockIdx.x * 256 + threadIdx.x) * 4;
    float4 val = *(const float4*)(s + i);
    uint4 o = make_uint4(f2tf32(val.x), f2tf32(val.y), f2tf32(val.z), f2tf32(val.w));
    *(uint4*)(d + i) = o;
}

__global__ __launch_bounds__(256)
void cvtw_kernel(const float* __restrict__ a, const float* __restrict__ b,
                 const float* __restrict__ c, const float* __restrict__ dd,
                 unsigned* __restrict__ oa, unsigned* __restrict__ ob,
                 unsigned* __restrict__ oc, unsigned* __restrict__ od)
{
    const float* s; unsigned* o;
    switch (blockIdx.y) {
        case 0: s = a;  o = oa; break;
        case 1: s = b;  o = ob; break;
        case 2: s = c;  o = oc; break;
        default: s = dd; o = od; break;
    }
    size_t i = ((size_t)blockIdx.x * 256 + threadIdx.x) * 4;
    float4 val = *(const float4*)(s + i);
    uint4 ov = make_uint4(f2tf32(val.x), f2tf32(val.y), f2tf32(val.z), f2tf32(val.w));
    *(uint4*)(o + i) = ov;
}

// ---------------- pipelined tf32 GEMM: 128x128, BK=32, cp.async 2-stage ------
// Operands are PRE-CONVERTED tf32 bits (unsigned). A row-major [m][k].
// MODE 0: projection scatter to [B,H,S,hd].  MODE 1: plain.
#define GM 4096
#define GN 1024
#define GK 1024
#define BM 128
#define BN 128
#define BKK 32
#define ALDA 36    // As stride: addr%32 = 4g+tq -> conflict-free A-frag loads
#define BLDB 136   // Bs stride: addr%32 = 8tq+g -> conflict-free B-frag loads

#define GEMM_SMEM ((2 * BM * ALDA + 2 * BKK * BLDB) * 4)

template <int MODE>
__global__ __launch_bounds__(256, 2)
void sgemm_pipe_kernel(const unsigned* __restrict__ A,
                       const unsigned* __restrict__ W,
                       float* __restrict__ C)
{
    extern __shared__ unsigned smem_u[];
    unsigned* As0 = smem_u;                       // [2][BM][ALDA]
    unsigned* Bs0 = smem_u + 2 * BM * ALDA;       // [2][BKK][BLDB]
#define AS(s, m, k) As0[(s) * BM * ALDA + (m) * ALDA + (k)]
#define BS(s, k, n) Bs0[(s) * BKK * BLDB + (k) * BLDB + (n)]

    const int tid  = threadIdx.x;
    const int m0   = blockIdx.x * BM;
    const int n0   = blockIdx.y * BN;
    const int warp = tid >> 5;
    const int lane = tid & 31;
    const int warpM = warp & 1;
    const int warpN = warp >> 1;
    const int g  = lane >> 2;
    const int tq = lane & 3;

    float acc[4][4][4];
#pragma unroll
    for (int i = 0; i < 4; i++)
#pragma unroll
        for (int j = 0; j < 4; j++)
#pragma unroll
            for (int r = 0; r < 4; r++) acc[i][j][r] = 0.f;

    // ---- tile loader (cp.async, one commit group per call)
    auto load_tile = [&](int k0, int s) {
#pragma unroll
        for (int p = 0; p < 4; p++) {
            int slot = tid + p * 256;            // 1024 16B chunks
            int row  = slot >> 3;                // 0..127
            int kq   = (slot & 7) * 4;           // 0..28
            cp16(&AS(s, row, kq), A + (size_t)(m0 + row) * GK + k0 + kq);
        }
#pragma unroll
        for (int p = 0; p < 4; p++) {
            int slot = tid + p * 256;
            int kk   = slot >> 5;                // 0..31
            int c4   = (slot & 31) * 4;          // 0..124
            const unsigned* src;
            if (MODE == 0) {
                int col = n0 + c4;
                int hh = col >> 6, e = col & 63;
                src = W + ((size_t)hh * GK + (k0 + kk)) * 64 + e;
            } else {
                src = W + (size_t)(k0 + kk) * GN + n0 + c4;
            }
            cp16(&BS(s, kk, c4), src);
        }
        asm volatile("cp.async.commit_group;");
    };

    const int NIT = GK / BKK;   // 32
    load_tile(0, 0);

    for (int it = 0; it < NIT; it++) {
        if (it + 1 < NIT) {
            load_tile((it + 1) * BKK, (it + 1) & 1);
            asm volatile("cp.async.wait_group 1;");
        } else {
            asm volatile("cp.async.wait_group 0;");
        }
        __syncthreads();

        const int s = it & 1;
#pragma unroll
        for (int ks = 0; ks < 4; ks++) {
            const int kb = ks * 8;
            unsigned a[4][4], b[4][2];
#pragma unroll
            for (int mf = 0; mf < 4; mf++) {
                int m = warpM * 64 + mf * 16 + g;
                a[mf][0] = AS(s, m,     kb + tq);
                a[mf][1] = AS(s, m + 8, kb + tq);
                a[mf][2] = AS(s, m,     kb + tq + 4);
                a[mf][3] = AS(s, m + 8, kb + tq + 4);
            }
#pragma unroll
            for (int nf = 0; nf < 4; nf++) {
                int n = warpN * 32 + nf * 8 + g;
                b[nf][0] = BS(s, kb + tq,     n);
                b[nf][1] = BS(s, kb + tq + 4, n);
            }
#pragma unroll
            for (int mf = 0; mf < 4; mf++)
#pragma unroll
                for (int nf = 0; nf < 4; nf++) {
                    asm volatile(
                        "mma.sync.aligned.m16n8k8.row.col.f32.tf32.tf32.f32 "
                        "{%0,%1,%2,%3}, {%4,%5,%6,%7}, {%8,%9}, {%0,%1,%2,%3};"
                        : "+f"(acc[mf][nf][0]), "+f"(acc[mf][nf][1]),
                          "+f"(acc[mf][nf][2]), "+f"(acc[mf][nf][3])
                        : "r"(a[mf][0]), "r"(a[mf][1]), "r"(a[mf][2]), "r"(a[mf][3]),
                          "r"(b[nf][0]), "r"(b[nf][1]));
                }
        }
        __syncthreads();
    }

    // ---- epilogue
#pragma unroll
    for (int mf = 0; mf < 4; mf++) {
#pragma unroll
        for (int nf = 0; nf < 4; nf++) {
            const int gcol = n0 + warpN * 32 + nf * 8 + 2 * tq;
#pragma unroll
            for (int half = 0; half < 2; half++) {
                const int grow = m0 + warpM * 64 + mf * 16 + g + half * 8;
                const float2 val = make_float2(acc[mf][nf][half * 2],
                                               acc[mf][nf][half * 2 + 1]);
                if (MODE == 0) {
                    const int bb = grow >> 11, ss = grow & 2047;
                    const int hh = gcol >> 6, e = gcol & 63;
                    *(float2*)(C + (((size_t)(bb * NHEAD + hh)) * SEQ + ss) * HDIM + e) = val;
                } else {
                    *(float2*)(C + (size_t)grow * GN + gcol) = val;
                }
            }
        }
    }
#undef AS
#undef BS
}

// ================= MMA flash attention (unchanged core) =====================
#define TQA 128
#define TKA 64
#define HST 72

#define ATTN_SMEM ((128 + 128 + 64 + 64 + 64) * HST * 2 + (128 + 64) * 4)

#define MMA16816(CC, A0, A1, A2, A3, B0, B1)                                  \
    asm volatile(                                                             \
        "mma.sync.aligned.m16n8k16.row.col.f32.f16.f16.f32 "                  \
        "{%0,%1,%2,%3}, {%4,%5,%6,%7}, {%8,%9}, {%0,%1,%2,%3};"               \
        : "+f"((CC)[0]), "+f"((CC)[1]), "+f"((CC)[2]), "+f"((CC)[3])          \
        : "r"(A0), "r"(A1), "r"(A2), "r"(A3), "r"(B0), "r"(B1))

__device__ __forceinline__ uint32_t pack_h2(float a, float b) {
    __half2 h = __floats2half2_rn(a, b);
    return *(uint32_t*)&h;
}

__device__ __forceinline__ void split_store(__half* hip, __half* lop,
                                            float x, float y) {
    __half hx = __float2half_rn(x), hy = __float2half_rn(y);
    float  rx = x - __half2float(hx), ry = y - __half2float(hy);
    *(uint32_t*)hip = pack_h2(__half2float(hx), __half2float(hy));
    *(uint32_t*)lop = pack_h2(rx, ry);
}

__global__ __launch_bounds__(256, 2)
void attn_mma_kernel(const float* __restrict__ QH, const float* __restrict__ KH,
                     const float* __restrict__ VH, const int* __restrict__ mask,
                     float* __restrict__ AO)
{
    extern __shared__ char smem_raw[];
    __half* Qhi = (__half*)smem_raw;
    __half* Qlo = Qhi + 128 * HST;
    __half* Khi = Qlo + 128 * HST;
    __half* Klo = Khi + 64 * HST;
    __half* Vs  = Klo + 64 * HST;
    int*    qm  = (int*)(Vs + 64 * HST);
    int*    km  = qm + 128;

    const int b = blockIdx.z, h = blockIdx.y;
    const int qt = (int)gridDim.x - 1 - (int)blockIdx.x;
    const int q0 = qt * TQA;
    const size_t base = ((size_t)(b * NHEAD + h)) * SEQ * HDIM;

    const int tid  = threadIdx.x;
    const int warp = tid >> 5, lane = tid & 31;
    const int g = lane >> 2, t = lane & 3;

#pragma unroll
    for (int p = 0; p < 8; p++) {
        int slot = tid + p * 256;
        int r  = slot >> 4;
        int d4 = (slot & 15) * 4;
        float4 v = *(const float4*)(QH + base + (size_t)(q0 + r) * HDIM + d4);
        v.x *= 0.125f; v.y *= 0.125f; v.z *= 0.125f; v.w *= 0.125f;
        split_store(&Qhi[r * HST + d4],     &Qlo[r * HST + d4],     v.x, v.y);
        split_store(&Qhi[r * HST + d4 + 2], &Qlo[r * HST + d4 + 2], v.z, v.w);
    }
    if (tid < 128) qm[tid] = mask[b * SEQ + q0 + tid];

    const int r0l = warp * 16 + g;
    const int r1l = r0l + 8;
    const int srow0 = q0 + r0l, srow1 = q0 + r1l;

    const float NEGINF = __int_as_float(0xff800000u);
    float m0 = NEGINF, m1 = NEGINF, l0 = 0.f, l1 = 0.f;
    float acc[8][4];
#pragma unroll
    for (int i = 0; i < 8; i++)
#pragma unroll
        for (int j = 0; j < 4; j++) acc[i][j] = 0.f;

    uint32_t vbase = (uint32_t)__cvta_generic_to_shared(Vs) +
                     (uint32_t)(lane & 15) * (HST * 2);

    const int ntiles = (q0 + TQA) / TKA;
    for (int kt = 0; kt < ntiles; kt++) {
        const int t0 = kt * TKA;
        __syncthreads();

#pragma unroll
        for (int p = 0; p < 4; p++) {
            int slot = tid + p * 256;
            int r  = slot >> 4;
            int d4 = (slot & 15) * 4;
            float4 kv = *(const float4*)(KH + base + (size_t)(t0 + r) * HDIM + d4);
            split_store(&Khi[r * HST + d4],     &Klo[r * HST + d4],     kv.x, kv.y);
            split_store(&Khi[r * HST + d4 + 2], &Klo[r * HST + d4 + 2], kv.z, kv.w);
            float4 vv = *(const float4*)(VH + base + (size_t)(t0 + r) * HDIM + d4);
            *(uint32_t*)&Vs[r * HST + d4]     = pack_h2(vv.x, vv.y);
            *(uint32_t*)&Vs[r * HST + d4 + 2] = pack_h2(vv.z, vv.w);
        }
        if (tid < 64) km[tid] = mask[b * SEQ + t0 + tid];
        __syncthreads();

        float sc[8][4];
#pragma unroll
        for (int i = 0; i < 8; i++)
#pragma unroll
            for (int j = 0; j < 4; j++) sc[i][j] = 0.f;

#pragma unroll
        for (int kj = 0; kj < 4; kj++) {
            const int koff = kj * 16 + 2 * t;
            uint32_t ah0 = *(const uint32_t*)&Qhi[r0l * HST + koff];
            uint32_t ah1 = *(const uint32_t*)&Qhi[r1l * HST + koff];
            uint32_t ah2 = *(const uint32_t*)&Qhi[r0l * HST + koff + 8];
            uint32_t ah3 = *(const uint32_t*)&Qhi[r1l * HST + koff + 8];
            uint32_t al0 = *(const uint32_t*)&Qlo[r0l * HST + koff];
            uint32_t al1 = *(const uint32_t*)&Qlo[r1l * HST + koff];
            uint32_t al2 = *(const uint32_t*)&Qlo[r0l * HST + koff + 8];
            uint32_t al3 = *(const uint32_t*)&Qlo[r1l * HST + koff + 8];
#pragma unroll
            for (int nf = 0; nf < 8; nf++) {
                const int krow = nf * 8 + g;
                uint32_t bh0 = *(const uint32_t*)&Khi[krow * HST + koff];
                uint32_t bh1 = *(const uint32_t*)&Khi[krow * HST + koff + 8];
                uint32_t bl0 = *(const uint32_t*)&Klo[krow * HST + koff];
                uint32_t bl1 = *(const uint32_t*)&Klo[krow * HST + koff + 8];
                MMA16816(sc[nf], ah0, ah1, ah2, ah3, bh0, bh1);
                MMA16816(sc[nf], ah0, ah1, ah2, ah3, bl0, bl1);
                MMA16816(sc[nf], al0, al1, al2, al3, bh0, bh1);
            }
        }

        const bool rm0 = (qm[r0l] != 0), rm1 = (qm[r1l] != 0);
        float mx0 = m0, mx1 = m1;
#pragma unroll
        for (int nf = 0; nf < 8; nf++) {
            const int c0i = nf * 8 + 2 * t, c1i = c0i + 1;
            const bool cm0 = (km[c0i] != 0), cm1 = (km[c1i] != 0);
            const int tc0 = t0 + c0i, tc1 = t0 + c1i;
            float v00 = (rm0 | cm0) ? 0.f : sc[nf][0]; if (tc0 > srow0) v00 = -1e30f;
            float v01 = (rm0 | cm1) ? 0.f : sc[nf][1]; if (tc1 > srow0) v01 = -1e30f;
            float v10 = (rm1 | cm0) ? 0.f : sc[nf][2]; if (tc0 > srow1) v10 = -1e30f;
            float v11 = (rm1 | cm1) ? 0.f : sc[nf][3]; if (tc1 > srow1) v11 = -1e30f;
            sc[nf][0] = v00; sc[nf][1] = v01; sc[nf][2] = v10; sc[nf][3] = v11;
            mx0 = fmaxf(mx0, fmaxf(v00, v01));
            mx1 = fmaxf(mx1, fmaxf(v10, v11));
        }
#pragma unroll
        for (int off = 1; off <= 2; off <<= 1) {
            mx0 = fmaxf(mx0, __shfl_xor_sync(0xffffffffu, mx0, off));
            mx1 = fmaxf(mx1, __shfl_xor_sync(0xffffffffu, mx1, off));
        }
        const float corr0 = __expf(m0 - mx0);
        const float corr1 = __expf(m1 - mx1);
        float rs0 = 0.f, rs1 = 0.f;
#pragma unroll
        for (int nf = 0; nf < 8; nf++) {
            float p00 = __expf(sc[nf][0] - mx0);
            float p01 = __expf(sc[nf][1] - mx0);
            float p10 = __expf(sc[nf][2] - mx1);
            float p11 = __expf(sc[nf][3] - mx1);
            sc[nf][0] = p00; sc[nf][1] = p01; sc[nf][2] = p10; sc[nf][3] = p11;
            rs0 += p00 + p01;
            rs1 += p10 + p11;
        }
#pragma unroll
        for (int off = 1; off <= 2; off <<= 1) {
            rs0 += __shfl_xor_sync(0xffffffffu, rs0, off);
            rs1 += __shfl_xor_sync(0xffffffffu, rs1, off);
        }
        l0 = l0 * corr0 + rs0;  m0 = mx0;
        l1 = l1 * corr1 + rs1;  m1 = mx1;
#pragma unroll
        for (int nfd = 0; nfd < 8; nfd++) {
            acc[nfd][0] *= corr0; acc[nfd][1] *= corr0;
            acc[nfd][2] *= corr1; acc[nfd][3] *= corr1;
        }

#pragma unroll
        for (int kj = 0; kj < 4; kj++) {
            uint32_t a0 = pack_h2(sc[2 * kj][0],     sc[2 * kj][1]);
            uint32_t a1 = pack_h2(sc[2 * kj][2],     sc[2 * kj][3]);
            uint32_t a2 = pack_h2(sc[2 * kj + 1][0], sc[2 * kj + 1][1]);
            uint32_t a3 = pack_h2(sc[2 * kj + 1][2], sc[2 * kj + 1][3]);
            const uint32_t vrow = vbase + (uint32_t)kj * 16 * (HST * 2);
#pragma unroll
            for (int nfd = 0; nfd < 8; nfd++) {
                uint32_t b0, b1;
                asm volatile(
                    "ldmatrix.sync.aligned.m8n8.x2.trans.shared.b16 {%0,%1}, [%2];"
                    : "=r"(b0), "=r"(b1)
                    : "r"(vrow + (uint32_t)nfd * 16));
                MMA16816(acc[nfd], a0, a1, a2, a3, b0, b1);
            }
        }
    }

    // ---- epilogue: normalize + convert to tf32 bits (feeds output GEMM)
    const float inv0 = 1.f / l0, inv1 = 1.f / l1;
#pragma unroll
    for (int nfd = 0; nfd < 8; nfd++) {
        const int dcol = nfd * 8 + 2 * t;
        *(float2*)(AO + base + (size_t)srow0 * HDIM + dcol) =
            make_float2(__uint_as_float(f2tf32(acc[nfd][0] * inv0)),
                        __uint_as_float(f2tf32(acc[nfd][1] * inv0)));
        *(float2*)(AO + base + (size_t)srow1 * HDIM + dcol) =
            make_float2(__uint_as_float(f2tf32(acc[nfd][2] * inv1)),
                        __uint_as_float(f2tf32(acc[nfd][3] * inv1)));
    }
}

// ---------------- launch -----------------------------------------------------
extern "C" void kernel_launch(void* const* d_in, const int* in_sizes, int n_in,
                              void* d_out, int out_size)
{
    const float* q    = (const float*)d_in[0];
    const float* k    = (const float*)d_in[1];
    const float* v    = (const float*)d_in[2];
    const float* Wq   = (const float*)d_in[3];
    const float* Wk   = (const float*)d_in[4];
    const float* Wv   = (const float*)d_in[5];
    const float* Wo   = (const float*)d_in[6];
    const int*   mask = (const int*)d_in[7];
    float* out = (float*)d_out;

    float *qh, *kh, *vh, *ao;
    unsigned *qt, *kt, *vt, *wq, *wk, *wv, *wo;
    cudaGetSymbolAddress((void**)&qh, g_qh);
    cudaGetSymbolAddress((void**)&kh, g_kh);
    cudaGetSymbolAddress((void**)&vh, g_vh);
    cudaGetSymbolAddress((void**)&ao, g_ao);
    cudaGetSymbolAddress((void**)&qt, g_qt);
    cudaGetSymbolAddress((void**)&kt, g_kt);
    cudaGetSymbolAddress((void**)&vt, g_vt);
    cudaGetSymbolAddress((void**)&wq, g_wq);
    cudaGetSymbolAddress((void**)&wk, g_wk);
    cudaGetSymbolAddress((void**)&wv, g_wv);
    cudaGetSymbolAddress((void**)&wo, g_wo);

    // preconvert inputs + weights to tf32 (rna)
    dim3 gc(BATCH * SEQ * DIMM / (256 * 4), 3);   // 4096 x 3
    cvtqkv_kernel<<<gc, 256>>>(q, k, v, qt, kt, vt);
    dim3 gw(NHEAD * DIMM * HDIM / (256 * 4), 4);  // 1024 x 4
    cvtw_kernel<<<gw, 256>>>(Wq, Wk, Wv, Wo, wq, wk, wv, wo);

    cudaFuncSetAttribute(sgemm_pipe_kernel<0>,
                         cudaFuncAttributeMaxDynamicSharedMemorySize, GEMM_SMEM);
    cudaFuncSetAttribute(sgemm_pipe_kernel<1>,
                         cudaFuncAttributeMaxDynamicSharedMemorySize, GEMM_SMEM);

    dim3 gg(GM / BM, GN / BN);   // 32 x 8
    sgemm_pipe_kernel<0><<<gg, 256, GEMM_SMEM>>>(qt, wq, qh);
    sgemm_pipe_kernel<0><<<gg, 256, GEMM_SMEM>>>(kt, wk, kh);
    sgemm_pipe_kernel<0><<<gg, 256, GEMM_SMEM>>>(vt, wv, vh);

    cudaFuncSetAttribute(attn_mma_kernel,
                         cudaFuncAttributeMaxDynamicSharedMemorySize, ATTN_SMEM);
    dim3 ga(SEQ / TQA, NHEAD, BATCH);   // 16 x 16 x 2
    attn_mma_kernel<<<ga, 256, ATTN_SMEM>>>(qh, kh, vh, mask, ao);

    sgemm_pipe_kernel<1><<<gg, 256, GEMM_SMEM>>>((const unsigned*)ao, wo, out);
}

// round 6
// speedup vs baseline: 3.6222x; 1.0031x over previous
#include <cuda_runtime.h>
#include <cuda_fp16.h>
#include <cstdint>

// Problem constants
#define BATCH   2
#define SEQ     2048
#define DIMM    1024
#define NHEAD   16
#define HDIM    64

// ---------------- scratch (allocation-free: device globals) ----------------
static __device__ float    g_qh[BATCH * NHEAD * SEQ * HDIM];
static __device__ float    g_kh[BATCH * NHEAD * SEQ * HDIM];
static __device__ float    g_vh[BATCH * NHEAD * SEQ * HDIM];
static __device__ float    g_ao[BATCH * NHEAD * SEQ * HDIM];   // tf32 bits
static __device__ unsigned g_qt[BATCH * SEQ * DIMM];           // tf32 inputs
static __device__ unsigned g_kt[BATCH * SEQ * DIMM];
static __device__ unsigned g_vt[BATCH * SEQ * DIMM];
static __device__ unsigned g_wq[NHEAD * DIMM * HDIM];          // tf32 weights
static __device__ unsigned g_wk[NHEAD * DIMM * HDIM];
static __device__ unsigned g_wv[NHEAD * DIMM * HDIM];
static __device__ unsigned g_wo[DIMM * DIMM];

// ---------------- helpers -----------------------------------------------------
__device__ __forceinline__ unsigned f2tf32(float x) {
    unsigned r;
    asm("cvt.rna.tf32.f32 %0, %1;" : "=r"(r) : "f"(x));
    return r;
}

__device__ __forceinline__ void cp16(void* smem_dst, const void* gmem_src) {
    uint32_t s = (uint32_t)__cvta_generic_to_shared(smem_dst);
    asm volatile("cp.async.cg.shared.global [%0], [%1], 16;"
                 :: "r"(s), "l"(gmem_src));
}

// ---------------- preconvert kernels -----------------------------------------
__global__ __launch_bounds__(256)
void cvtqkv_kernel(const float* __restrict__ q, const float* __restrict__ k,
                   const float* __restrict__ v,
                   unsigned* __restrict__ oq, unsigned* __restrict__ ok,
                   unsigned* __restrict__ ov)
{
    const float* s = (blockIdx.y == 0) ? q : (blockIdx.y == 1) ? k : v;
    unsigned*    d = (blockIdx.y == 0) ? oq : (blockIdx.y == 1) ? ok : ov;
    size_t i = ((size_t)blockIdx.x * 256 + threadIdx.x) * 4;
    float4 val = *(const float4*)(s + i);
    uint4 o = make_uint4(f2tf32(val.x), f2tf32(val.y), f2tf32(val.z), f2tf32(val.w));
    *(uint4*)(d + i) = o;
}

__global__ __launch_bounds__(256)
void cvtw_kernel(const float* __restrict__ a, const float* __restrict__ b,
                 const float* __restrict__ c, const float* __restrict__ dd,
                 unsigned* __restrict__ oa, unsigned* __restrict__ ob,
                 unsigned* __restrict__ oc, unsigned* __restrict__ od)
{
    const float* s; unsigned* o;
    switch (blockIdx.y) {
        case 0: s = a;  o = oa; break;
        case 1: s = b;  o = ob; break;
        case 2: s = c;  o = oc; break;
        default: s = dd; o = od; break;
    }
    size_t i = ((size_t)blockIdx.x * 256 + threadIdx.x) * 4;
    float4 val = *(const float4*)(s + i);
    uint4 ov = make_uint4(f2tf32(val.x), f2tf32(val.y), f2tf32(val.z), f2tf32(val.w));
    *(uint4*)(o + i) = ov;
}

// ---------------- pipelined tf32 GEMM: 128x128, BK=32, cp.async 3-stage ------
// Pre-converted tf32 operands. One __syncthreads per mainloop iteration.
// MODE 0: projection scatter to [B,H,S,hd], blockIdx.z selects (q|k|v).
// MODE 1: plain GEMM (z=0).
#define GM 4096
#define GN 1024
#define GK 1024
#define BM 128
#define BN 128
#define BKK 32
#define ALDA 36    // As stride: addr%32 = 4g+tq -> conflict-free A-frag loads
#define BLDB 136   // Bs stride: addr%32 = 8tq+g -> conflict-free B-frag loads
#define STAGES 3

#define GEMM_SMEM (STAGES * (BM * ALDA + BKK * BLDB) * 4)

template <int MODE>
__global__ __launch_bounds__(256, 2)
void gemm3_kernel(const unsigned* __restrict__ A0, const unsigned* __restrict__ A1,
                  const unsigned* __restrict__ A2,
                  const unsigned* __restrict__ W0, const unsigned* __restrict__ W1,
                  const unsigned* __restrict__ W2,
                  float* __restrict__ C0, float* __restrict__ C1,
                  float* __restrict__ C2)
{
    extern __shared__ unsigned smem_u[];
    unsigned* As0 = smem_u;                              // [STAGES][BM][ALDA]
    unsigned* Bs0 = smem_u + STAGES * BM * ALDA;         // [STAGES][BKK][BLDB]
#define AS(s, m, k) As0[(s) * BM * ALDA + (m) * ALDA + (k)]
#define BS(s, k, n) Bs0[(s) * BKK * BLDB + (k) * BLDB + (n)]

    const int z = blockIdx.z;
    const unsigned* A = (z == 0) ? A0 : (z == 1) ? A1 : A2;
    const unsigned* W = (z == 0) ? W0 : (z == 1) ? W1 : W2;
    float*          C = (z == 0) ? C0 : (z == 1) ? C1 : C2;

    const int tid  = threadIdx.x;
    const int m0   = blockIdx.x * BM;
    const int n0   = blockIdx.y * BN;
    const int warp = tid >> 5;
    const int lane = tid & 31;
    const int warpM = warp & 1;
    const int warpN = warp >> 1;
    const int g  = lane >> 2;
    const int tq = lane & 3;

    float acc[4][4][4];
#pragma unroll
    for (int i = 0; i < 4; i++)
#pragma unroll
        for (int j = 0; j < 4; j++)
#pragma unroll
            for (int r = 0; r < 4; r++) acc[i][j][r] = 0.f;

    auto load_tile = [&](int k0, int s) {
#pragma unroll
        for (int p = 0; p < 4; p++) {
            int slot = tid + p * 256;            // 1024 16B chunks
            int row  = slot >> 3;                // 0..127
            int kq   = (slot & 7) * 4;           // 0..28
            cp16(&AS(s, row, kq), A + (size_t)(m0 + row) * GK + k0 + kq);
        }
#pragma unroll
        for (int p = 0; p < 4; p++) {
            int slot = tid + p * 256;
            int kk   = slot >> 5;                // 0..31
            int c4   = (slot & 31) * 4;          // 0..124
            const unsigned* src;
            if (MODE == 0) {
                int col = n0 + c4;
                int hh = col >> 6, e = col & 63;
                src = W + ((size_t)hh * GK + (k0 + kk)) * 64 + e;
            } else {
                src = W + (size_t)(k0 + kk) * GN + n0 + c4;
            }
            cp16(&BS(s, kk, c4), src);
        }
        asm volatile("cp.async.commit_group;");
    };

    const int NIT = GK / BKK;   // 32
    load_tile(0, 0);
    load_tile(BKK, 1);

    int s = 0;
    for (int it = 0; it < NIT; it++) {
        if (it + 1 < NIT) {
            asm volatile("cp.async.wait_group 1;");   // oldest (tile it) done
        } else {
            asm volatile("cp.async.wait_group 0;");
        }
        __syncthreads();   // all warps: tile it visible AND compute(it-1) done

        if (it + 2 < NIT) {
            int sl = s + 2; if (sl >= STAGES) sl -= STAGES;
            load_tile((it + 2) * BKK, sl);
        }

#pragma unroll
        for (int ks = 0; ks < 4; ks++) {
            const int kb = ks * 8;
            unsigned a[4][4], b[4][2];
#pragma unroll
            for (int mf = 0; mf < 4; mf++) {
                int m = warpM * 64 + mf * 16 + g;
                a[mf][0] = AS(s, m,     kb + tq);
                a[mf][1] = AS(s, m + 8, kb + tq);
                a[mf][2] = AS(s, m,     kb + tq + 4);
                a[mf][3] = AS(s, m + 8, kb + tq + 4);
            }
#pragma unroll
            for (int nf = 0; nf < 4; nf++) {
                int n = warpN * 32 + nf * 8 + g;
                b[nf][0] = BS(s, kb + tq,     n);
                b[nf][1] = BS(s, kb + tq + 4, n);
            }
#pragma unroll
            for (int mf = 0; mf < 4; mf++)
#pragma unroll
                for (int nf = 0; nf < 4; nf++) {
                    asm volatile(
                        "mma.sync.aligned.m16n8k8.row.col.f32.tf32.tf32.f32 "
                        "{%0,%1,%2,%3}, {%4,%5,%6,%7}, {%8,%9}, {%0,%1,%2,%3};"
                        : "+f"(acc[mf][nf][0]), "+f"(acc[mf][nf][1]),
                          "+f"(acc[mf][nf][2]), "+f"(acc[mf][nf][3])
                        : "r"(a[mf][0]), "r"(a[mf][1]), "r"(a[mf][2]), "r"(a[mf][3]),
                          "r"(b[nf][0]), "r"(b[nf][1]));
                }
        }
        s = s + 1; if (s >= STAGES) s -= STAGES;
    }

    // ---- epilogue
#pragma unroll
    for (int mf = 0; mf < 4; mf++) {
#pragma unroll
        for (int nf = 0; nf < 4; nf++) {
            const int gcol = n0 + warpN * 32 + nf * 8 + 2 * tq;
#pragma unroll
            for (int half = 0; half < 2; half++) {
                const int grow = m0 + warpM * 64 + mf * 16 + g + half * 8;
                const float2 val = make_float2(acc[mf][nf][half * 2],
                                               acc[mf][nf][half * 2 + 1]);
                if (MODE == 0) {
                    const int bb = grow >> 11, ss = grow & 2047;
                    const int hh = gcol >> 6, e = gcol & 63;
                    *(float2*)(C + (((size_t)(bb * NHEAD + hh)) * SEQ + ss) * HDIM + e) = val;
                } else {
                    *(float2*)(C + (size_t)grow * GN + gcol) = val;
                }
            }
        }
    }
#undef AS
#undef BS
}

// ================= MMA flash attention (cp.async K/V prefetch) ==============
#define TQA 128
#define TKA 64
#define HST 72

// smem: float stage (K 4096 + V 4096 floats) + half tiles + masks
#define ATTN_STAGE_FLOATS (2 * TKA * HDIM)
#define ATTN_SMEM (ATTN_STAGE_FLOATS * 4 + (128 + 128 + 64 + 64 + 64) * HST * 2 + (128 + 64) * 4)

#define MMA16816(CC, A0, A1, A2, A3, B0, B1)                                  \
    asm volatile(                                                             \
        "mma.sync.aligned.m16n8k16.row.col.f32.f16.f16.f32 "                  \
        "{%0,%1,%2,%3}, {%4,%5,%6,%7}, {%8,%9}, {%0,%1,%2,%3};"               \
        : "+f"((CC)[0]), "+f"((CC)[1]), "+f"((CC)[2]), "+f"((CC)[3])          \
        : "r"(A0), "r"(A1), "r"(A2), "r"(A3), "r"(B0), "r"(B1))

__device__ __forceinline__ uint32_t pack_h2(float a, float b) {
    __half2 h = __floats2half2_rn(a, b);
    return *(uint32_t*)&h;
}

__device__ __forceinline__ void split_store(__half* hip, __half* lop,
                                            float x, float y) {
    __half hx = __float2half_rn(x), hy = __float2half_rn(y);
    float  rx = x - __half2float(hx), ry = y - __half2float(hy);
    *(uint32_t*)hip = pack_h2(__half2float(hx), __half2float(hy));
    *(uint32_t*)lop = pack_h2(rx, ry);
}

__global__ __launch_bounds__(256, 2)
void attn_mma_kernel(const float* __restrict__ QH, const float* __restrict__ KH,
                     const float* __restrict__ VH, const int* __restrict__ mask,
                     float* __restrict__ AO)
{
    extern __shared__ char smem_raw[];
    float*  Kst = (float*)smem_raw;                 // [64][64] float staging
    float*  Vst = Kst + TKA * HDIM;
    __half* Qhi = (__half*)(Vst + TKA * HDIM);
    __half* Qlo = Qhi + 128 * HST;
    __half* Khi = Qlo + 128 * HST;
    __half* Klo = Khi + 64 * HST;
    __half* Vs  = Klo + 64 * HST;
    int*    qm  = (int*)(Vs + 64 * HST);
    int*    km  = qm + 128;

    const int b = blockIdx.z, h = blockIdx.y;
    const int qt = (int)gridDim.x - 1 - (int)blockIdx.x;   // heavy tiles first
    const int q0 = qt * TQA;
    const size_t base = ((size_t)(b * NHEAD + h)) * SEQ * HDIM;

    const int tid  = threadIdx.x;
    const int warp = tid >> 5, lane = tid & 31;
    const int g = lane >> 2, t = lane & 3;

    // ---- issue cp.async for K/V tile 0 immediately
    {
#pragma unroll
        for (int p = 0; p < 4; p++) {
            int slot = tid + p * 256;            // 1024 16B chunks
            int r  = slot >> 4;
            int d4 = (slot & 15) * 4;
            cp16(&Kst[r * HDIM + d4], KH + base + (size_t)r * HDIM + d4);
            cp16(&Vst[r * HDIM + d4], VH + base + (size_t)r * HDIM + d4);
        }
        asm volatile("cp.async.commit_group;");
    }

    // ---- load Q tile: scale 1/8, split to fp16 hi/lo
#pragma unroll
    for (int p = 0; p < 8; p++) {
        int slot = tid + p * 256;
        int r  = slot >> 4;
        int d4 = (slot & 15) * 4;
        float4 v = *(const float4*)(QH + base + (size_t)(q0 + r) * HDIM + d4);
        v.x *= 0.125f; v.y *= 0.125f; v.z *= 0.125f; v.w *= 0.125f;
        split_store(&Qhi[r * HST + d4],     &Qlo[r * HST + d4],     v.x, v.y);
        split_store(&Qhi[r * HST + d4 + 2], &Qlo[r * HST + d4 + 2], v.z, v.w);
    }
    if (tid < 128) qm[tid] = mask[b * SEQ + q0 + tid];

    const int r0l = warp * 16 + g;
    const int r1l = r0l + 8;
    const int srow0 = q0 + r0l, srow1 = q0 + r1l;

    const float NEGINF = __int_as_float(0xff800000u);
    float m0 = NEGINF, m1 = NEGINF, l0 = 0.f, l1 = 0.f;
    float acc[8][4];
#pragma unroll
    for (int i = 0; i < 8; i++)
#pragma unroll
        for (int j = 0; j < 4; j++) acc[i][j] = 0.f;

    uint32_t vbase = (uint32_t)__cvta_generic_to_shared(Vs) +
                     (uint32_t)(lane & 15) * (HST * 2);

    const int ntiles = (q0 + TQA) / TKA;
    for (int kt = 0; kt < ntiles; kt++) {
        const int t0 = kt * TKA;
        asm volatile("cp.async.wait_group 0;");   // tile kt staged
        __syncthreads();   // staging visible to all; prior compute reads done

        // ---- convert staged K (split fp16) and V (fp16) into half tiles
#pragma unroll
        for (int p = 0; p < 4; p++) {
            int slot = tid + p * 256;
            int r  = slot >> 4;
            int d4 = (slot & 15) * 4;
            float4 kv = *(const float4*)&Kst[r * HDIM + d4];
            split_store(&Khi[r * HST + d4],     &Klo[r * HST + d4],     kv.x, kv.y);
            split_store(&Khi[r * HST + d4 + 2], &Klo[r * HST + d4 + 2], kv.z, kv.w);
            float4 vv = *(const float4*)&Vst[r * HDIM + d4];
            *(uint32_t*)&Vs[r * HST + d4]     = pack_h2(vv.x, vv.y);
            *(uint32_t*)&Vs[r * HST + d4 + 2] = pack_h2(vv.z, vv.w);
        }
        if (tid < 64) km[tid] = mask[b * SEQ + t0 + tid];
        __syncthreads();   // halves ready; staging reads complete

        // ---- prefetch NEXT tile into staging (overlapped with compute)
        if (kt + 1 < ntiles) {
            const size_t nb = base + (size_t)(t0 + TKA) * HDIM;
#pragma unroll
            for (int p = 0; p < 4; p++) {
                int slot = tid + p * 256;
                int r  = slot >> 4;
                int d4 = (slot & 15) * 4;
                cp16(&Kst[r * HDIM + d4], KH + nb + (size_t)r * HDIM + d4);
                cp16(&Vst[r * HDIM + d4], VH + nb + (size_t)r * HDIM + d4);
            }
            asm volatile("cp.async.commit_group;");
        }

        // ---- QK
        float sc[8][4];
#pragma unroll
        for (int i = 0; i < 8; i++)
#pragma unroll
            for (int j = 0; j < 4; j++) sc[i][j] = 0.f;

#pragma unroll
        for (int kj = 0; kj < 4; kj++) {
            const int koff = kj * 16 + 2 * t;
            uint32_t ah0 = *(const uint32_t*)&Qhi[r0l * HST + koff];
            uint32_t ah1 = *(const uint32_t*)&Qhi[r1l * HST + koff];
            uint32_t ah2 = *(const uint32_t*)&Qhi[r0l * HST + koff + 8];
            uint32_t ah3 = *(const uint32_t*)&Qhi[r1l * HST + koff + 8];
            uint32_t al0 = *(const uint32_t*)&Qlo[r0l * HST + koff];
            uint32_t al1 = *(const uint32_t*)&Qlo[r1l * HST + koff];
            uint32_t al2 = *(const uint32_t*)&Qlo[r0l * HST + koff + 8];
            uint32_t al3 = *(const uint32_t*)&Qlo[r1l * HST + koff + 8];
#pragma unroll
            for (int nf = 0; nf < 8; nf++) {
                const int krow = nf * 8 + g;
                uint32_t bh0 = *(const uint32_t*)&Khi[krow * HST + koff];
                uint32_t bh1 = *(const uint32_t*)&Khi[krow * HST + koff + 8];
                uint32_t bl0 = *(const uint32_t*)&Klo[krow * HST + koff];
                uint32_t bl1 = *(const uint32_t*)&Klo[krow * HST + koff + 8];
                MMA16816(sc[nf], ah0, ah1, ah2, ah3, bh0, bh1);
                MMA16816(sc[nf], ah0, ah1, ah2, ah3, bl0, bl1);
                MMA16816(sc[nf], al0, al1, al2, al3, bh0, bh1);
            }
        }

        // ---- mask + online softmax (warp-local)
        const bool rm0 = (qm[r0l] != 0), rm1 = (qm[r1l] != 0);
        float mx0 = m0, mx1 = m1;
#pragma unroll
        for (int nf = 0; nf < 8; nf++) {
            const int c0i = nf * 8 + 2 * t, c1i = c0i + 1;
            const bool cm0 = (km[c0i] != 0), cm1 = (km[c1i] != 0);
            const int tc0 = t0 + c0i, tc1 = t0 + c1i;
            float v00 = (rm0 | cm0) ? 0.f : sc[nf][0]; if (tc0 > srow0) v00 = -1e30f;
            float v01 = (rm0 | cm1) ? 0.f : sc[nf][1]; if (tc1 > srow0) v01 = -1e30f;
            float v10 = (rm1 | cm0) ? 0.f : sc[nf][2]; if (tc0 > srow1) v10 = -1e30f;
            float v11 = (rm1 | cm1) ? 0.f : sc[nf][3]; if (tc1 > srow1) v11 = -1e30f;
            sc[nf][0] = v00; sc[nf][1] = v01; sc[nf][2] = v10; sc[nf][3] = v11;
            mx0 = fmaxf(mx0, fmaxf(v00, v01));
            mx1 = fmaxf(mx1, fmaxf(v10, v11));
        }
#pragma unroll
        for (int off = 1; off <= 2; off <<= 1) {
            mx0 = fmaxf(mx0, __shfl_xor_sync(0xffffffffu, mx0, off));
            mx1 = fmaxf(mx1, __shfl_xor_sync(0xffffffffu, mx1, off));
        }
        const float corr0 = __expf(m0 - mx0);
        const float corr1 = __expf(m1 - mx1);
        float rs0 = 0.f, rs1 = 0.f;
#pragma unroll
        for (int nf = 0; nf < 8; nf++) {
            float p00 = __expf(sc[nf][0] - mx0);
            float p01 = __expf(sc[nf][1] - mx0);
            float p10 = __expf(sc[nf][2] - mx1);
            float p11 = __expf(sc[nf][3] - mx1);
            sc[nf][0] = p00; sc[nf][1] = p01; sc[nf][2] = p10; sc[nf][3] = p11;
            rs0 += p00 + p01;
            rs1 += p10 + p11;
        }
#pragma unroll
        for (int off = 1; off <= 2; off <<= 1) {
            rs0 += __shfl_xor_sync(0xffffffffu, rs0, off);
            rs1 += __shfl_xor_sync(0xffffffffu, rs1, off);
        }
        l0 = l0 * corr0 + rs0;  m0 = mx0;
        l1 = l1 * corr1 + rs1;  m1 = mx1;
#pragma unroll
        for (int nfd = 0; nfd < 8; nfd++) {
            acc[nfd][0] *= corr0; acc[nfd][1] *= corr0;
            acc[nfd][2] *= corr1; acc[nfd][3] *= corr1;
        }

        // ---- PV
#pragma unroll
        for (int kj = 0; kj < 4; kj++) {
            uint32_t a0 = pack_h2(sc[2 * kj][0],     sc[2 * kj][1]);
            uint32_t a1 = pack_h2(sc[2 * kj][2],     sc[2 * kj][3]);
            uint32_t a2 = pack_h2(sc[2 * kj + 1][0], sc[2 * kj + 1][1]);
            uint32_t a3 = pack_h2(sc[2 * kj + 1][2], sc[2 * kj + 1][3]);
            const uint32_t vrow = vbase + (uint32_t)kj * 16 * (HST * 2);
#pragma unroll
            for (int nfd = 0; nfd < 8; nfd++) {
                uint32_t b0, b1;
                asm volatile(
                    "ldmatrix.sync.aligned.m8n8.x2.trans.shared.b16 {%0,%1}, [%2];"
                    : "=r"(b0), "=r"(b1)
                    : "r"(vrow + (uint32_t)nfd * 16));
                MMA16816(acc[nfd], a0, a1, a2, a3, b0, b1);
            }
        }
    }

    // ---- epilogue: normalize + tf32-round (feeds output GEMM)
    const float inv0 = 1.f / l0, inv1 = 1.f / l1;
#pragma unroll
    for (int nfd = 0; nfd < 8; nfd++) {
        const int dcol = nfd * 8 + 2 * t;
        *(float2*)(AO + base + (size_t)srow0 * HDIM + dcol) =
            make_float2(__uint_as_float(f2tf32(acc[nfd][0] * inv0)),
                        __uint_as_float(f2tf32(acc[nfd][1] * inv0)));
        *(float2*)(AO + base + (size_t)srow1 * HDIM + dcol) =
            make_float2(__uint_as_float(f2tf32(acc[nfd][2] * inv1)),
                        __uint_as_float(f2tf32(acc[nfd][3] * inv1)));
    }
}

// ---------------- launch -----------------------------------------------------
extern "C" void kernel_launch(void* const* d_in, const int* in_sizes, int n_in,
                              void* d_out, int out_size)
{
    const float* q    = (const float*)d_in[0];
    const float* k    = (const float*)d_in[1];
    const float* v    = (const float*)d_in[2];
    const float* Wq   = (const float*)d_in[3];
    const float* Wk   = (const float*)d_in[4];
    const float* Wv   = (const float*)d_in[5];
    const float* Wo   = (const float*)d_in[6];
    const int*   mask = (const int*)d_in[7];
    float* out = (float*)d_out;

    float *qh, *kh, *vh, *ao;
    unsigned *qt, *kt, *vt, *wq, *wk, *wv, *wo;
    cudaGetSymbolAddress((void**)&qh, g_qh);
    cudaGetSymbolAddress((void**)&kh, g_kh);
    cudaGetSymbolAddress((void**)&vh, g_vh);
    cudaGetSymbolAddress((void**)&ao, g_ao);
    cudaGetSymbolAddress((void**)&qt, g_qt);
    cudaGetSymbolAddress((void**)&kt, g_kt);
    cudaGetSymbolAddress((void**)&vt, g_vt);
    cudaGetSymbolAddress((void**)&wq, g_wq);
    cudaGetSymbolAddress((void**)&wk, g_wk);
    cudaGetSymbolAddress((void**)&wv, g_wv);
    cudaGetSymbolAddress((void**)&wo, g_wo);

    // preconvert inputs + weights to tf32 (rna)
    dim3 gc(BATCH * SEQ * DIMM / (256 * 4), 3);
    cvtqkv_kernel<<<gc, 256>>>(q, k, v, qt, kt, vt);
    dim3 gw(NHEAD * DIMM * HDIM / (256 * 4), 4);
    cvtw_kernel<<<gw, 256>>>(Wq, Wk, Wv, Wo, wq, wk, wv, wo);

    cudaFuncSetAttribute(gemm3_kernel<0>,
                         cudaFuncAttributeMaxDynamicSharedMemorySize, GEMM_SMEM);
    cudaFuncSetAttribute(gemm3_kernel<1>,
                         cudaFuncAttributeMaxDynamicSharedMemorySize, GEMM_SMEM);

    // fused q/k/v projections: grid.z selects tensor
    dim3 gp(GM / BM, GN / BN, 3);   // 32 x 8 x 3
    gemm3_kernel<0><<<gp, 256, GEMM_SMEM>>>(qt, kt, vt, wq, wk, wv, qh, kh, vh);

    cudaFuncSetAttribute(attn_mma_kernel,
                         cudaFuncAttributeMaxDynamicSharedMemorySize, ATTN_SMEM);
    dim3 ga(SEQ / TQA, NHEAD, BATCH);   // 16 x 16 x 2
    attn_mma_kernel<<<ga, 256, ATTN_SMEM>>>(qh, kh, vh, mask, ao);

    dim3 go(GM / BM, GN / BN, 1);
    gemm3_kernel<1><<<go, 256, GEMM_SMEM>>>((const unsigned*)ao, (const unsigned*)ao,
                                            (const unsigned*)ao, wo, wo, wo,
                                            out, out, out);
}

// round 7
// speedup vs baseline: 3.8039x; 1.0502x over previous
#include <cuda_runtime.h>
#include <cuda_fp16.h>
#include <cstdint>

// Problem constants
#define BATCH   2
#define SEQ     2048
#define DIMM    1024
#define NHEAD   16
#define HDIM    64

// ---------------- scratch (allocation-free: device globals) ----------------
static __device__ float    g_qh[BATCH * NHEAD * SEQ * HDIM];
static __device__ float    g_kh[BATCH * NHEAD * SEQ * HDIM];
static __device__ float    g_vh[BATCH * NHEAD * SEQ * HDIM];
static __device__ float    g_ao[BATCH * NHEAD * SEQ * HDIM];   // tf32 bits
static __device__ unsigned g_qt[BATCH * SEQ * DIMM];           // tf32 inputs
static __device__ unsigned g_kt[BATCH * SEQ * DIMM];
static __device__ unsigned g_vt[BATCH * SEQ * DIMM];
static __device__ unsigned g_wq[NHEAD * DIMM * HDIM];          // tf32 weights
static __device__ unsigned g_wk[NHEAD * DIMM * HDIM];
static __device__ unsigned g_wv[NHEAD * DIMM * HDIM];
static __device__ unsigned g_wo[DIMM * DIMM];

// ---------------- helpers -----------------------------------------------------
__device__ __forceinline__ unsigned f2tf32(float x) {
    unsigned r;
    asm("cvt.rna.tf32.f32 %0, %1;" : "=r"(r) : "f"(x));
    return r;
}

__device__ __forceinline__ float ex2(float x) {
    float y;
    asm("ex2.approx.ftz.f32 %0, %1;" : "=f"(y) : "f"(x));
    return y;
}

__device__ __forceinline__ void cp16(void* smem_dst, const void* gmem_src) {
    uint32_t s = (uint32_t)__cvta_generic_to_shared(smem_dst);
    asm volatile("cp.async.cg.shared.global [%0], [%1], 16;"
                 :: "r"(s), "l"(gmem_src));
}

// ---------------- preconvert kernels -----------------------------------------
__global__ __launch_bounds__(256)
void cvtqkv_kernel(const float* __restrict__ q, const float* __restrict__ k,
                   const float* __restrict__ v,
                   unsigned* __restrict__ oq, unsigned* __restrict__ ok,
                   unsigned* __restrict__ ov)
{
    const float* s = (blockIdx.y == 0) ? q : (blockIdx.y == 1) ? k : v;
    unsigned*    d = (blockIdx.y == 0) ? oq : (blockIdx.y == 1) ? ok : ov;
    size_t i = ((size_t)blockIdx.x * 256 + threadIdx.x) * 4;
    float4 val = *(const float4*)(s + i);
    uint4 o = make_uint4(f2tf32(val.x), f2tf32(val.y), f2tf32(val.z), f2tf32(val.w));
    *(uint4*)(d + i) = o;
}

__global__ __launch_bounds__(256)
void cvtw_kernel(const float* __restrict__ a, const float* __restrict__ b,
                 const float* __restrict__ c, const float* __restrict__ dd,
                 unsigned* __restrict__ oa, unsigned* __restrict__ ob,
                 unsigned* __restrict__ oc, unsigned* __restrict__ od)
{
    const float* s; unsigned* o;
    switch (blockIdx.y) {
        case 0: s = a;  o = oa; break;
        case 1: s = b;  o = ob; break;
        case 2: s = c;  o = oc; break;
        default: s = dd; o = od; break;
    }
    size_t i = ((size_t)blockIdx.x * 256 + threadIdx.x) * 4;
    float4 val = *(const float4*)(s + i);
    uint4 ov = make_uint4(f2tf32(val.x), f2tf32(val.y), f2tf32(val.z), f2tf32(val.w));
    *(uint4*)(o + i) = ov;
}

// ---------------- pipelined tf32 GEMM (unchanged from R6) --------------------
#define GM 4096
#define GN 1024
#define GK 1024
#define BM 128
#define BN 128
#define BKK 32
#define ALDA 36
#define BLDB 136
#define STAGES 3

#define GEMM_SMEM (STAGES * (BM * ALDA + BKK * BLDB) * 4)

template <int MODE>
__global__ __launch_bounds__(256, 2)
void gemm3_kernel(const unsigned* __restrict__ A0, const unsigned* __restrict__ A1,
                  const unsigned* __restrict__ A2,
                  const unsigned* __restrict__ W0, const unsigned* __restrict__ W1,
                  const unsigned* __restrict__ W2,
                  float* __restrict__ C0, float* __restrict__ C1,
                  float* __restrict__ C2)
{
    extern __shared__ unsigned smem_u[];
    unsigned* As0 = smem_u;
    unsigned* Bs0 = smem_u + STAGES * BM * ALDA;
#define AS(s, m, k) As0[(s) * BM * ALDA + (m) * ALDA + (k)]
#define BS(s, k, n) Bs0[(s) * BKK * BLDB + (k) * BLDB + (n)]

    const int z = blockIdx.z;
    const unsigned* A = (z == 0) ? A0 : (z == 1) ? A1 : A2;
    const unsigned* W = (z == 0) ? W0 : (z == 1) ? W1 : W2;
    float*          C = (z == 0) ? C0 : (z == 1) ? C1 : C2;

    const int tid  = threadIdx.x;
    const int m0   = blockIdx.x * BM;
    const int n0   = blockIdx.y * BN;
    const int warp = tid >> 5;
    const int lane = tid & 31;
    const int warpM = warp & 1;
    const int warpN = warp >> 1;
    const int g  = lane >> 2;
    const int tq = lane & 3;

    float acc[4][4][4];
#pragma unroll
    for (int i = 0; i < 4; i++)
#pragma unroll
        for (int j = 0; j < 4; j++)
#pragma unroll
            for (int r = 0; r < 4; r++) acc[i][j][r] = 0.f;

    auto load_tile = [&](int k0, int s) {
#pragma unroll
        for (int p = 0; p < 4; p++) {
            int slot = tid + p * 256;
            int row  = slot >> 3;
            int kq   = (slot & 7) * 4;
            cp16(&AS(s, row, kq), A + (size_t)(m0 + row) * GK + k0 + kq);
        }
#pragma unroll
        for (int p = 0; p < 4; p++) {
            int slot = tid + p * 256;
            int kk   = slot >> 5;
            int c4   = (slot & 31) * 4;
            const unsigned* src;
            if (MODE == 0) {
                int col = n0 + c4;
                int hh = col >> 6, e = col & 63;
                src = W + ((size_t)hh * GK + (k0 + kk)) * 64 + e;
            } else {
                src = W + (size_t)(k0 + kk) * GN + n0 + c4;
            }
            cp16(&BS(s, kk, c4), src);
        }
        asm volatile("cp.async.commit_group;");
    };

    const int NIT = GK / BKK;
    load_tile(0, 0);
    load_tile(BKK, 1);

    int s = 0;
    for (int it = 0; it < NIT; it++) {
        if (it + 1 < NIT) {
            asm volatile("cp.async.wait_group 1;");
        } else {
            asm volatile("cp.async.wait_group 0;");
        }
        __syncthreads();

        if (it + 2 < NIT) {
            int sl = s + 2; if (sl >= STAGES) sl -= STAGES;
            load_tile((it + 2) * BKK, sl);
        }

#pragma unroll
        for (int ks = 0; ks < 4; ks++) {
            const int kb = ks * 8;
            unsigned a[4][4], b[4][2];
#pragma unroll
            for (int mf = 0; mf < 4; mf++) {
                int m = warpM * 64 + mf * 16 + g;
                a[mf][0] = AS(s, m,     kb + tq);
                a[mf][1] = AS(s, m + 8, kb + tq);
                a[mf][2] = AS(s, m,     kb + tq + 4);
                a[mf][3] = AS(s, m + 8, kb + tq + 4);
            }
#pragma unroll
            for (int nf = 0; nf < 4; nf++) {
                int n = warpN * 32 + nf * 8 + g;
                b[nf][0] = BS(s, kb + tq,     n);
                b[nf][1] = BS(s, kb + tq + 4, n);
            }
#pragma unroll
            for (int mf = 0; mf < 4; mf++)
#pragma unroll
                for (int nf = 0; nf < 4; nf++) {
                    asm volatile(
                        "mma.sync.aligned.m16n8k8.row.col.f32.tf32.tf32.f32 "
                        "{%0,%1,%2,%3}, {%4,%5,%6,%7}, {%8,%9}, {%0,%1,%2,%3};"
                        : "+f"(acc[mf][nf][0]), "+f"(acc[mf][nf][1]),
                          "+f"(acc[mf][nf][2]), "+f"(acc[mf][nf][3])
                        : "r"(a[mf][0]), "r"(a[mf][1]), "r"(a[mf][2]), "r"(a[mf][3]),
                          "r"(b[nf][0]), "r"(b[nf][1]));
                }
        }
        s = s + 1; if (s >= STAGES) s -= STAGES;
    }

#pragma unroll
    for (int mf = 0; mf < 4; mf++) {
#pragma unroll
        for (int nf = 0; nf < 4; nf++) {
            const int gcol = n0 + warpN * 32 + nf * 8 + 2 * tq;
#pragma unroll
            for (int half = 0; half < 2; half++) {
                const int grow = m0 + warpM * 64 + mf * 16 + g + half * 8;
                const float2 val = make_float2(acc[mf][nf][half * 2],
                                               acc[mf][nf][half * 2 + 1]);
                if (MODE == 0) {
                    const int bb = grow >> 11, ss = grow & 2047;
                    const int hh = gcol >> 6, e = gcol & 63;
                    *(float2*)(C + (((size_t)(bb * NHEAD + hh)) * SEQ + ss) * HDIM + e) = val;
                } else {
                    *(float2*)(C + (size_t)grow * GN + gcol) = val;
                }
            }
        }
    }
#undef AS
#undef BS
}

// ================= MMA flash attention: ldmatrix + log2 softmax =============
#define TQA 128
#define TKA 64
#define HST 72   // halves per row (144 B): 16B-aligned, conflict-free ldmatrix

#define ATTN_STAGE_FLOATS (2 * TKA * HDIM)
#define ATTN_SMEM (ATTN_STAGE_FLOATS * 4 + (128 + 128 + 64 + 64 + 64) * HST * 2 + (128 + 64) * 4)

#define MMA16816(CC, A0, A1, A2, A3, B0, B1)                                  \
    asm volatile(                                                             \
        "mma.sync.aligned.m16n8k16.row.col.f32.f16.f16.f32 "                  \
        "{%0,%1,%2,%3}, {%4,%5,%6,%7}, {%8,%9}, {%0,%1,%2,%3};"               \
        : "+f"((CC)[0]), "+f"((CC)[1]), "+f"((CC)[2]), "+f"((CC)[3])          \
        : "r"(A0), "r"(A1), "r"(A2), "r"(A3), "r"(B0), "r"(B1))

#define LDSM_X4(R0, R1, R2, R3, ADDR)                                         \
    asm volatile("ldmatrix.sync.aligned.m8n8.x4.shared.b16 {%0,%1,%2,%3}, [%4];" \
                 : "=r"(R0), "=r"(R1), "=r"(R2), "=r"(R3) : "r"(ADDR))

#define LDSM_X4T(R0, R1, R2, R3, ADDR)                                        \
    asm volatile("ldmatrix.sync.aligned.m8n8.x4.trans.shared.b16 {%0,%1,%2,%3}, [%4];" \
                 : "=r"(R0), "=r"(R1), "=r"(R2), "=r"(R3) : "r"(ADDR))

__device__ __forceinline__ uint32_t pack_h2(float a, float b) {
    __half2 h = __floats2half2_rn(a, b);
    return *(uint32_t*)&h;
}

__device__ __forceinline__ void split_store(__half* hip, __half* lop,
                                            float x, float y) {
    __half hx = __float2half_rn(x), hy = __float2half_rn(y);
    float  rx = x - __half2float(hx), ry = y - __half2float(hy);
    *(uint32_t*)hip = pack_h2(__half2float(hx), __half2float(hy));
    *(uint32_t*)lop = pack_h2(rx, ry);
}

__global__ __launch_bounds__(256, 2)
void attn_mma_kernel(const float* __restrict__ QH, const float* __restrict__ KH,
                     const float* __restrict__ VH, const int* __restrict__ mask,
                     float* __restrict__ AO)
{
    extern __shared__ char smem_raw[];
    float*  Kst = (float*)smem_raw;                 // [64][64] float staging
    float*  Vst = Kst + TKA * HDIM;
    __half* Qhi = (__half*)(Vst + TKA * HDIM);
    __half* Qlo = Qhi + 128 * HST;
    __half* Khi = Qlo + 128 * HST;
    __half* Klo = Khi + 64 * HST;
    __half* Vs  = Klo + 64 * HST;
    int*    qm  = (int*)(Vs + 64 * HST);
    int*    km  = qm + 128;

    const int b = blockIdx.z, h = blockIdx.y;
    const int qt = (int)gridDim.x - 1 - (int)blockIdx.x;   // heavy tiles first
    const int q0 = qt * TQA;
    const size_t base = ((size_t)(b * NHEAD + h)) * SEQ * HDIM;

    const int tid  = threadIdx.x;
    const int warp = tid >> 5, lane = tid & 31;
    const int g = lane >> 2, t = lane & 3;

    // ---- issue cp.async for K/V tile 0 immediately
    {
#pragma unroll
        for (int p = 0; p < 4; p++) {
            int slot = tid + p * 256;
            int r  = slot >> 4;
            int d4 = (slot & 15) * 4;
            cp16(&Kst[r * HDIM + d4], KH + base + (size_t)r * HDIM + d4);
            cp16(&Vst[r * HDIM + d4], VH + base + (size_t)r * HDIM + d4);
        }
        asm volatile("cp.async.commit_group;");
    }

    // ---- load Q tile: scale by log2e/8, split to fp16 hi/lo
    const float QSCALE = 0.125f * 1.44269504088896f;   // log2 domain
#pragma unroll
    for (int p = 0; p < 8; p++) {
        int slot = tid + p * 256;
        int r  = slot >> 4;
        int d4 = (slot & 15) * 4;
        float4 v = *(const float4*)(QH + base + (size_t)(q0 + r) * HDIM + d4);
        v.x *= QSCALE; v.y *= QSCALE; v.z *= QSCALE; v.w *= QSCALE;
        split_store(&Qhi[r * HST + d4],     &Qlo[r * HST + d4],     v.x, v.y);
        split_store(&Qhi[r * HST + d4 + 2], &Qlo[r * HST + d4 + 2], v.z, v.w);
    }
    if (tid < 128) qm[tid] = mask[b * SEQ + q0 + tid];

    const int r0l = warp * 16 + g;
    const int r1l = r0l + 8;
    const int srow0 = q0 + r0l, srow1 = q0 + r1l;

    const float NEGINF = __int_as_float(0xff800000u);
    float m0 = NEGINF, m1 = NEGINF, l0 = 0.f, l1 = 0.f;
    float acc[8][4];
#pragma unroll
    for (int i = 0; i < 8; i++)
#pragma unroll
        for (int j = 0; j < 4; j++) acc[i][j] = 0.f;

    // ---- per-lane ldmatrix base offsets (bytes)
    const uint32_t qhiB = (uint32_t)__cvta_generic_to_shared(Qhi);
    const uint32_t qloB = (uint32_t)__cvta_generic_to_shared(Qlo);
    const uint32_t khiB = (uint32_t)__cvta_generic_to_shared(Khi);
    const uint32_t kloB = (uint32_t)__cvta_generic_to_shared(Klo);
    const uint32_t vB   = (uint32_t)__cvta_generic_to_shared(Vs);
    // Q A-frag: lanes 0-15 rows m0-15 @ col 0; lanes 16-31 same rows @ col+8h
    const uint32_t qoff = (uint32_t)(((warp * 16 + (lane & 15)) * HST
                                      + (lane >> 4) * 8) * 2);
    // K B-frag x4 (nf pair): lanes0-7 n0-7@k0, 8-15 n0-7@k8, 16-23 n8-15@k0, 24-31 n8-15@k8
    const uint32_t koff = (uint32_t)(((((lane >> 4) * 8) + (lane & 7)) * HST
                                      + ((lane >> 3) & 1) * 8) * 2);
    // V B-frag x4.trans (nfd pair): lanes0-15 rows c0-15 @ col 2p*8h; 16-31 @ +8h
    const uint32_t voff = (uint32_t)(((lane & 15) * HST + (lane >> 4) * 8) * 2);

    const int ntiles = (q0 + TQA) / TKA;
    for (int kt = 0; kt < ntiles; kt++) {
        const int t0 = kt * TKA;
        asm volatile("cp.async.wait_group 0;");
        __syncthreads();

        // ---- convert staged K (split fp16) and V (fp16) into half tiles
#pragma unroll
        for (int p = 0; p < 4; p++) {
            int slot = tid + p * 256;
            int r  = slot >> 4;
            int d4 = (slot & 15) * 4;
            float4 kv = *(const float4*)&Kst[r * HDIM + d4];
            split_store(&Khi[r * HST + d4],     &Klo[r * HST + d4],     kv.x, kv.y);
            split_store(&Khi[r * HST + d4 + 2], &Klo[r * HST + d4 + 2], kv.z, kv.w);
            float4 vv = *(const float4*)&Vst[r * HDIM + d4];
            *(uint32_t*)&Vs[r * HST + d4]     = pack_h2(vv.x, vv.y);
            *(uint32_t*)&Vs[r * HST + d4 + 2] = pack_h2(vv.z, vv.w);
        }
        if (tid < 64) km[tid] = mask[b * SEQ + t0 + tid];
        __syncthreads();

        // ---- prefetch NEXT tile into staging (overlaps compute)
        if (kt + 1 < ntiles) {
            const size_t nb = base + (size_t)(t0 + TKA) * HDIM;
#pragma unroll
            for (int p = 0; p < 4; p++) {
                int slot = tid + p * 256;
                int r  = slot >> 4;
                int d4 = (slot & 15) * 4;
                cp16(&Kst[r * HDIM + d4], KH + nb + (size_t)r * HDIM + d4);
                cp16(&Vst[r * HDIM + d4], VH + nb + (size_t)r * HDIM + d4);
            }
            asm volatile("cp.async.commit_group;");
        }

        // ---- QK via ldmatrix
        float sc[8][4];
#pragma unroll
        for (int i = 0; i < 8; i++)
#pragma unroll
            for (int j = 0; j < 4; j++) sc[i][j] = 0.f;

#pragma unroll
        for (int kj = 0; kj < 4; kj++) {
            uint32_t ah0, ah1, ah2, ah3, al0, al1, al2, al3;
            LDSM_X4(ah0, ah1, ah2, ah3, qhiB + qoff + kj * 32);
            LDSM_X4(al0, al1, al2, al3, qloB + qoff + kj * 32);
#pragma unroll
            for (int nfp = 0; nfp < 4; nfp++) {
                const uint32_t kk = koff + (uint32_t)((nfp * 16 * HST + kj * 16) * 2);
                uint32_t bh0, bh1, bh2, bh3, bl0, bl1, bl2, bl3;
                LDSM_X4(bh0, bh1, bh2, bh3, khiB + kk);
                LDSM_X4(bl0, bl1, bl2, bl3, kloB + kk);
                MMA16816(sc[2 * nfp],     ah0, ah1, ah2, ah3, bh0, bh1);
                MMA16816(sc[2 * nfp],     ah0, ah1, ah2, ah3, bl0, bl1);
                MMA16816(sc[2 * nfp],     al0, al1, al2, al3, bh0, bh1);
                MMA16816(sc[2 * nfp + 1], ah0, ah1, ah2, ah3, bh2, bh3);
                MMA16816(sc[2 * nfp + 1], ah0, ah1, ah2, ah3, bl2, bl3);
                MMA16816(sc[2 * nfp + 1], al0, al1, al2, al3, bh2, bh3);
            }
        }

        // ---- mask + online softmax (log2 domain, warp-local)
        const bool rm0 = (qm[r0l] != 0), rm1 = (qm[r1l] != 0);
        float mx0 = m0, mx1 = m1;
#pragma unroll
        for (int nf = 0; nf < 8; nf++) {
            const int c0i = nf * 8 + 2 * t, c1i = c0i + 1;
            const bool cm0 = (km[c0i] != 0), cm1 = (km[c1i] != 0);
            const int tc0 = t0 + c0i, tc1 = t0 + c1i;
            float v00 = (rm0 | cm0) ? 0.f : sc[nf][0]; if (tc0 > srow0) v00 = -1e30f;
            float v01 = (rm0 | cm1) ? 0.f : sc[nf][1]; if (tc1 > srow0) v01 = -1e30f;
            float v10 = (rm1 | cm0) ? 0.f : sc[nf][2]; if (tc0 > srow1) v10 = -1e30f;
            float v11 = (rm1 | cm1) ? 0.f : sc[nf][3]; if (tc1 > srow1) v11 = -1e30f;
            sc[nf][0] = v00; sc[nf][1] = v01; sc[nf][2] = v10; sc[nf][3] = v11;
            mx0 = fmaxf(mx0, fmaxf(v00, v01));
            mx1 = fmaxf(mx1, fmaxf(v10, v11));
        }
#pragma unroll
        for (int off = 1; off <= 2; off <<= 1) {
            mx0 = fmaxf(mx0, __shfl_xor_sync(0xffffffffu, mx0, off));
            mx1 = fmaxf(mx1, __shfl_xor_sync(0xffffffffu, mx1, off));
        }
        const float corr0 = ex2(m0 - mx0);
        const float corr1 = ex2(m1 - mx1);
        float rs0 = 0.f, rs1 = 0.f;
#pragma unroll
        for (int nf = 0; nf < 8; nf++) {
            float p00 = ex2(sc[nf][0] - mx0);
            float p01 = ex2(sc[nf][1] - mx0);
            float p10 = ex2(sc[nf][2] - mx1);
            float p11 = ex2(sc[nf][3] - mx1);
            sc[nf][0] = p00; sc[nf][1] = p01; sc[nf][2] = p10; sc[nf][3] = p11;
            rs0 += p00 + p01;
            rs1 += p10 + p11;
        }
#pragma unroll
        for (int off = 1; off <= 2; off <<= 1) {
            rs0 += __shfl_xor_sync(0xffffffffu, rs0, off);
            rs1 += __shfl_xor_sync(0xffffffffu, rs1, off);
        }
        l0 = l0 * corr0 + rs0;  m0 = mx0;
        l1 = l1 * corr1 + rs1;  m1 = mx1;
#pragma unroll
        for (int nfd = 0; nfd < 8; nfd++) {
            acc[nfd][0] *= corr0; acc[nfd][1] *= corr0;
            acc[nfd][2] *= corr1; acc[nfd][3] *= corr1;
        }

        // ---- PV: P (register re-pack) x V (ldmatrix.x4.trans)
#pragma unroll
        for (int kj = 0; kj < 4; kj++) {
            uint32_t a0 = pack_h2(sc[2 * kj][0],     sc[2 * kj][1]);
            uint32_t a1 = pack_h2(sc[2 * kj][2],     sc[2 * kj][3]);
            uint32_t a2 = pack_h2(sc[2 * kj + 1][0], sc[2 * kj + 1][1]);
            uint32_t a3 = pack_h2(sc[2 * kj + 1][2], sc[2 * kj + 1][3]);
            const uint32_t vrow = vB + voff + (uint32_t)((kj * 16 * HST) * 2);
#pragma unroll
            for (int p = 0; p < 4; p++) {
                uint32_t b0, b1, b2, b3;
                LDSM_X4T(b0, b1, b2, b3, vrow + (uint32_t)(p * 32));
                MMA16816(acc[2 * p],     a0, a1, a2, a3, b0, b1);
                MMA16816(acc[2 * p + 1], a0, a1, a2, a3, b2, b3);
            }
        }
    }

    // ---- epilogue: normalize + tf32-round (feeds output GEMM)
    const float inv0 = 1.f / l0, inv1 = 1.f / l1;
#pragma unroll
    for (int nfd = 0; nfd < 8; nfd++) {
        const int dcol = nfd * 8 + 2 * t;
        *(float2*)(AO + base + (size_t)srow0 * HDIM + dcol) =
            make_float2(__uint_as_float(f2tf32(acc[nfd][0] * inv0)),
                        __uint_as_float(f2tf32(acc[nfd][1] * inv0)));
        *(float2*)(AO + base + (size_t)srow1 * HDIM + dcol) =
            make_float2(__uint_as_float(f2tf32(acc[nfd][2] * inv1)),
                        __uint_as_float(f2tf32(acc[nfd][3] * inv1)));
    }
}

// ---------------- launch -----------------------------------------------------
extern "C" void kernel_launch(void* const* d_in, const int* in_sizes, int n_in,
                              void* d_out, int out_size)
{
    const float* q    = (const float*)d_in[0];
    const float* k    = (const float*)d_in[1];
    const float* v    = (const float*)d_in[2];
    const float* Wq   = (const float*)d_in[3];
    const float* Wk   = (const float*)d_in[4];
    const float* Wv   = (const float*)d_in[5];
    const float* Wo   = (const float*)d_in[6];
    const int*   mask = (const int*)d_in[7];
    float* out = (float*)d_out;

    float *qh, *kh, *vh, *ao;
    unsigned *qt, *kt, *vt, *wq, *wk, *wv, *wo;
    cudaGetSymbolAddress((void**)&qh, g_qh);
    cudaGetSymbolAddress((void**)&kh, g_kh);
    cudaGetSymbolAddress((void**)&vh, g_vh);
    cudaGetSymbolAddress((void**)&ao, g_ao);
    cudaGetSymbolAddress((void**)&qt, g_qt);
    cudaGetSymbolAddress((void**)&kt, g_kt);
    cudaGetSymbolAddress((void**)&vt, g_vt);
    cudaGetSymbolAddress((void**)&wq, g_wq);
    cudaGetSymbolAddress((void**)&wk, g_wk);
    cudaGetSymbolAddress((void**)&wv, g_wv);
    cudaGetSymbolAddress((void**)&wo, g_wo);

    dim3 gc(BATCH * SEQ * DIMM / (256 * 4), 3);
    cvtqkv_kernel<<<gc, 256>>>(q, k, v, qt, kt, vt);
    dim3 gw(NHEAD * DIMM * HDIM / (256 * 4), 4);
    cvtw_kernel<<<gw, 256>>>(Wq, Wk, Wv, Wo, wq, wk, wv, wo);

    cudaFuncSetAttribute(gemm3_kernel<0>,
                         cudaFuncAttributeMaxDynamicSharedMemorySize, GEMM_SMEM);
    cudaFuncSetAttribute(gemm3_kernel<1>,
                         cudaFuncAttributeMaxDynamicSharedMemorySize, GEMM_SMEM);

    dim3 gp(GM / BM, GN / BN, 3);
    gemm3_kernel<0><<<gp, 256, GEMM_SMEM>>>(qt, kt, vt, wq, wk, wv, qh, kh, vh);

    cudaFuncSetAttribute(attn_mma_kernel,
                         cudaFuncAttributeMaxDynamicSharedMemorySize, ATTN_SMEM);
    dim3 ga(SEQ / TQA, NHEAD, BATCH);
    attn_mma_kernel<<<ga, 256, ATTN_SMEM>>>(qh, kh, vh, mask, ao);

    dim3 go(GM / BM, GN / BN, 1);
    gemm3_kernel<1><<<go, 256, GEMM_SMEM>>>((const unsigned*)ao, (const unsigned*)ao,
                                            (const unsigned*)ao, wo, wo, wo,
                                            out, out, out);
}

// round 10
// speedup vs baseline: 3.8763x; 1.0190x over previous
#include <cuda_runtime.h>
#include <cuda_fp16.h>
#include <cstdint>

// Problem constants
#define BATCH   2
#define SEQ     2048
#define DIMM    1024
#define NHEAD   16
#define HDIM    64

#define GM 4096
#define GN 1024
#define GK 1024

#define QSCALE (0.125f * 1.44269504088896f)   // 1/sqrt(64) * log2(e)

// ---------------- scratch (allocation-free: device globals) ----------------
static __device__ float    g_ao[BATCH * NHEAD * SEQ * HDIM];   // tf32 bits
static __device__ unsigned g_qt[GM * GK];                      // tf32 inputs
static __device__ unsigned g_kt[GM * GK];
static __device__ unsigned g_vt[GM * GK];
static __device__ unsigned g_wq[GN * GK];                      // tf32 weights
static __device__ unsigned g_wk[GN * GK];
static __device__ unsigned g_wv[GN * GK];
static __device__ unsigned g_wo[GN * GK];
// fp16 attention operands, [B,H,S,hd], written by projection GEMM epilogue
static __device__ __half g_q16h[BATCH * NHEAD * SEQ * HDIM];
static __device__ __half g_q16l[BATCH * NHEAD * SEQ * HDIM];
static __device__ __half g_k16h[BATCH * NHEAD * SEQ * HDIM];
static __device__ __half g_k16l[BATCH * NHEAD * SEQ * HDIM];
static __device__ __half g_v16 [BATCH * NHEAD * SEQ * HDIM];

// ---------------- helpers -----------------------------------------------------
__device__ __forceinline__ unsigned f2tf32(float x) {
    unsigned r;
    asm("cvt.rna.tf32.f32 %0, %1;" : "=r"(r) : "f"(x));
    return r;
}
__device__ __forceinline__ float ex2(float x) {
    float y;
    asm("ex2.approx.ftz.f32 %0, %1;" : "=f"(y) : "f"(x));
    return y;
}
__device__ __forceinline__ void cp16s(uint32_t smem_dst, const void* gmem_src) {
    asm volatile("cp.async.cg.shared.global [%0], [%1], 16;"
                 :: "r"(smem_dst), "l"(gmem_src));
}

// ---------------- preconvert kernels -----------------------------------------
__global__ __launch_bounds__(256)
void cvtqkv_kernel(const float* __restrict__ q, const float* __restrict__ k,
                   const float* __restrict__ v)
{
    const float* s = (blockIdx.y == 0) ? q : (blockIdx.y == 1) ? k : v;
    unsigned*    d = (blockIdx.y == 0) ? g_qt : (blockIdx.y == 1) ? g_kt : g_vt;
    size_t i = ((size_t)blockIdx.x * 256 + threadIdx.x) * 4;
    float4 val = *(const float4*)(s + i);
    uint4 o = make_uint4(f2tf32(val.x), f2tf32(val.y), f2tf32(val.z), f2tf32(val.w));
    *(uint4*)(d + i) = o;
}

__global__ __launch_bounds__(256)
void cvtw_kernel(const float* __restrict__ a, const float* __restrict__ b,
                 const float* __restrict__ c, const float* __restrict__ dd)
{
    const float* s; unsigned* o;
    switch (blockIdx.y) {
        case 0: s = a;  o = g_wq; break;
        case 1: s = b;  o = g_wk; break;
        case 2: s = c;  o = g_wv; break;
        default: s = dd; o = g_wo; break;
    }
    size_t i = ((size_t)blockIdx.x * 256 + threadIdx.x) * 4;
    float4 val = *(const float4*)(s + i);
    uint4 ov = make_uint4(f2tf32(val.x), f2tf32(val.y), f2tf32(val.z), f2tf32(val.w));
    *(uint4*)(o + i) = ov;
}

// ---------------- pipelined tf32 GEMM: 128x128, BK=32, cp.async 3-stage ------
// MODE 0: projection; z selects q/k/v; epilogue writes fp16 hi/lo [B,H,S,hd]
//         (z=0 scaled by QSCALE; z=2 writes single fp16 V).
// MODE 1: plain GEMM -> f32 C.
#define BM 128
#define BN 128
#define BKK 32
#define ALDA 36    // addr%32 = 4g+tq -> conflict-free A-frag loads
#define BLDB 136   // >= BN=128 (row width!) and addr%32 = 8tq+g conflict-free
#define STAGES 3

#define GEMM_SMEM (STAGES * (BM * ALDA + BKK * BLDB) * 4)   // 107,520 B

template <int MODE>
__global__ __launch_bounds__(256, 2)
void gemm3_kernel(const unsigned* __restrict__ A0, const unsigned* __restrict__ A1,
                  const unsigned* __restrict__ A2,
                  const unsigned* __restrict__ W0, const unsigned* __restrict__ W1,
                  const unsigned* __restrict__ W2,
                  __half* __restrict__ H0, __half* __restrict__ L0,
                  __half* __restrict__ H1, __half* __restrict__ L1,
                  __half* __restrict__ H2,
                  float* __restrict__ C)
{
    extern __shared__ unsigned smem_u[];
    unsigned* As0 = smem_u;                              // [STAGES][BM][ALDA]
    unsigned* Bs0 = smem_u + STAGES * BM * ALDA;         // [STAGES][BKK][BLDB]
#define AS(s, m, k) As0[(s) * BM * ALDA + (m) * ALDA + (k)]
#define BS(s, k, n) Bs0[(s) * BKK * BLDB + (k) * BLDB + (n)]

    const int z = blockIdx.z;
    const unsigned* A = (z == 0) ? A0 : (z == 1) ? A1 : A2;
    const unsigned* W = (z == 0) ? W0 : (z == 1) ? W1 : W2;

    const int tid  = threadIdx.x;
    const int m0   = blockIdx.x * BM;
    const int n0   = blockIdx.y * BN;
    const int warp = tid >> 5;
    const int lane = tid & 31;
    const int warpM = warp & 1;
    const int warpN = warp >> 1;
    const int g  = lane >> 2;
    const int tq = lane & 3;

    float acc[4][4][4];
#pragma unroll
    for (int i = 0; i < 4; i++)
#pragma unroll
        for (int j = 0; j < 4; j++)
#pragma unroll
            for (int r = 0; r < 4; r++) acc[i][j][r] = 0.f;

    const uint32_t smU = (uint32_t)__cvta_generic_to_shared(smem_u);

    auto load_tile = [&](int k0, int s) {
#pragma unroll
        for (int p = 0; p < 4; p++) {
            int slot = tid + p * 256;
            int row  = slot >> 3;
            int kq   = (slot & 7) * 4;
            cp16s(smU + (uint32_t)((s * BM * ALDA + row * ALDA + kq) * 4),
                  A + (size_t)(m0 + row) * GK + k0 + kq);
        }
#pragma unroll
        for (int p = 0; p < 4; p++) {
            int slot = tid + p * 256;
            int kk   = slot >> 5;
            int c4   = (slot & 31) * 4;
            const unsigned* src;
            if (MODE == 0) {
                int col = n0 + c4;
                int hh = col >> 6, e = col & 63;
                src = W + ((size_t)hh * GK + (k0 + kk)) * 64 + e;
            } else {
                src = W + (size_t)(k0 + kk) * GN + n0 + c4;
            }
            cp16s(smU + (uint32_t)((STAGES * BM * ALDA + s * BKK * BLDB
                                    + kk * BLDB + c4) * 4), src);
        }
        asm volatile("cp.async.commit_group;");
    };

    const int NIT = GK / BKK;
    load_tile(0, 0);
    load_tile(BKK, 1);

    int s = 0;
    for (int it = 0; it < NIT; it++) {
        if (it + 1 < NIT) {
            asm volatile("cp.async.wait_group 1;");
        } else {
            asm volatile("cp.async.wait_group 0;");
        }
        __syncthreads();

        if (it + 2 < NIT) {
            int sl = s + 2; if (sl >= STAGES) sl -= STAGES;
            load_tile((it + 2) * BKK, sl);
        }

#pragma unroll
        for (int ks = 0; ks < 4; ks++) {
            const int kb = ks * 8;
            unsigned a[4][4], b[4][2];
#pragma unroll
            for (int mf = 0; mf < 4; mf++) {
                int m = warpM * 64 + mf * 16 + g;
                a[mf][0] = AS(s, m,     kb + tq);
                a[mf][1] = AS(s, m + 8, kb + tq);
                a[mf][2] = AS(s, m,     kb + tq + 4);
                a[mf][3] = AS(s, m + 8, kb + tq + 4);
            }
#pragma unroll
            for (int nf = 0; nf < 4; nf++) {
                int n = warpN * 32 + nf * 8 + g;
                b[nf][0] = BS(s, kb + tq,     n);
                b[nf][1] = BS(s, kb + tq + 4, n);
            }
#pragma unroll
            for (int mf = 0; mf < 4; mf++)
#pragma unroll
                for (int nf = 0; nf < 4; nf++) {
                    asm volatile(
                        "mma.sync.aligned.m16n8k8.row.col.f32.tf32.tf32.f32 "
                        "{%0,%1,%2,%3}, {%4,%5,%6,%7}, {%8,%9}, {%0,%1,%2,%3};"
                        : "+f"(acc[mf][nf][0]), "+f"(acc[mf][nf][1]),
                          "+f"(acc[mf][nf][2]), "+f"(acc[mf][nf][3])
                        : "r"(a[mf][0]), "r"(a[mf][1]), "r"(a[mf][2]), "r"(a[mf][3]),
                          "r"(b[nf][0]), "r"(b[nf][1]));
                }
        }
        s = s + 1; if (s >= STAGES) s -= STAGES;
    }

    // ---- epilogue
    const float scl = (MODE == 0 && z == 0) ? QSCALE : 1.f;
    __half* OH = (z == 0) ? H0 : (z == 1) ? H1 : H2;
    __half* OL = (z == 0) ? L0 : L1;                 // unused for z==2
#pragma unroll
    for (int mf = 0; mf < 4; mf++) {
#pragma unroll
        for (int nf = 0; nf < 4; nf++) {
            const int gcol = n0 + warpN * 32 + nf * 8 + 2 * tq;
#pragma unroll
            for (int half = 0; half < 2; half++) {
                const int grow = m0 + warpM * 64 + mf * 16 + g + half * 8;
                float x0 = acc[mf][nf][half * 2]     * scl;
                float x1 = acc[mf][nf][half * 2 + 1] * scl;
                if (MODE == 0) {
                    const int bb = grow >> 11, ss = grow & 2047;
                    const int hh = gcol >> 6, e = gcol & 63;
                    const size_t idx =
                        (((size_t)(bb * NHEAD + hh)) * SEQ + ss) * HDIM + e;
                    __half h0 = __float2half_rn(x0);
                    __half h1 = __float2half_rn(x1);
                    __half2 hv; hv.x = h0; hv.y = h1;
                    *(__half2*)(OH + idx) = hv;
                    if (z < 2) {
                        __half l0 = __float2half_rn(x0 - __half2float(h0));
                        __half l1 = __float2half_rn(x1 - __half2float(h1));
                        __half2 lv; lv.x = l0; lv.y = l1;
                        *(__half2*)(OL + idx) = lv;
                    }
                } else {
                    *(float2*)(C + (size_t)grow * GN + gcol) =
                        make_float2(x0, x1);
                }
            }
        }
    }
#undef AS
#undef BS
}

// ================= MMA flash attention: direct fp16 tiles ===================
// Operands pre-split to fp16 by the projection epilogue. Per k-tile: one
// cp.async group (K hi/lo, V, masks), one __syncthreads, pure mma compute.
#define TQA 128
#define TKA 64

// smem (bytes): Qhi 18432 | Qlo 18432 | stage0 27648 | stage1 27648 | qm 512 | km 512
#define OFF_QHI 0
#define OFF_QLO 18432
#define OFF_STG 36864
#define STG_B   27648     // Khi 9216 + Klo 9216 + V 9216
#define OFF_QM  92160
#define OFF_KM  92672
#define ATTN_SMEM 93696

#define MMA16816(CC, A0, A1, A2, A3, B0, B1)                                  \
    asm volatile(                                                             \
        "mma.sync.aligned.m16n8k16.row.col.f32.f16.f16.f32 "                  \
        "{%0,%1,%2,%3}, {%4,%5,%6,%7}, {%8,%9}, {%0,%1,%2,%3};"               \
        : "+f"((CC)[0]), "+f"((CC)[1]), "+f"((CC)[2]), "+f"((CC)[3])          \
        : "r"(A0), "r"(A1), "r"(A2), "r"(A3), "r"(B0), "r"(B1))

#define LDSM_X4(R0, R1, R2, R3, ADDR)                                         \
    asm volatile("ldmatrix.sync.aligned.m8n8.x4.shared.b16 {%0,%1,%2,%3}, [%4];" \
                 : "=r"(R0), "=r"(R1), "=r"(R2), "=r"(R3) : "r"(ADDR))

#define LDSM_X4T(R0, R1, R2, R3, ADDR)                                        \
    asm volatile("ldmatrix.sync.aligned.m8n8.x4.trans.shared.b16 {%0,%1,%2,%3}, [%4];" \
                 : "=r"(R0), "=r"(R1), "=r"(R2), "=r"(R3) : "r"(ADDR))

__device__ __forceinline__ uint32_t pack_h2(float a, float b) {
    __half2 h = __floats2half2_rn(a, b);
    return *(uint32_t*)&h;
}

__global__ __launch_bounds__(256, 2)
void attn_mma_kernel(const __half* __restrict__ QHI, const __half* __restrict__ QLO,
                     const __half* __restrict__ KHI, const __half* __restrict__ KLO,
                     const __half* __restrict__ V16, const int* __restrict__ mask,
                     float* __restrict__ AO)
{
    extern __shared__ char smem_raw[];
    const uint32_t smU = (uint32_t)__cvta_generic_to_shared(smem_raw);

    const int b = blockIdx.z, h = blockIdx.y;
    const int qt = (int)gridDim.x - 1 - (int)blockIdx.x;   // heavy tiles first
    const int q0 = qt * TQA;
    const size_t base = ((size_t)(b * NHEAD + h)) * SEQ * HDIM;
    const int mrow = b * SEQ;

    const int tid  = threadIdx.x;
    const int warp = tid >> 5, lane = tid & 31;
    const int g = lane >> 2, t = lane & 3;

    // ---- tile loader: stage s <- k-tile starting at t0n (K hi/lo + V + km)
    auto load_tile = [&](int t0n, int s) {
        const uint32_t sb = smU + OFF_STG + (uint32_t)s * STG_B;
#pragma unroll
        for (int p = 0; p < 6; p++) {
            int slot = tid + p * 256;            // 0..1535
            int arr  = slot >> 9;                // 0=Khi 1=Klo 2=V
            int rem  = slot & 511;
            int r    = rem >> 3;
            int cB   = (rem & 7) * 16;           // byte col within 128B row
            const __half* src = (arr == 0) ? KHI : (arr == 1) ? KLO : V16;
            cp16s(sb + (uint32_t)(arr * 9216 + r * 144 + cB),
                  src + base + (size_t)(t0n + r) * HDIM + (cB >> 1));
        }
        if (tid < 16)
            cp16s(smU + OFF_KM + (uint32_t)(s * 256 + tid * 16),
                  mask + mrow + t0n + tid * 4);
        asm volatile("cp.async.commit_group;");
    };

    // ---- prologue: Q hi/lo + qm + tile 0, one group
    {
#pragma unroll
        for (int p = 0; p < 8; p++) {
            int slot = tid + p * 256;            // 0..2047
            int arr  = slot >> 10;               // 0=Qhi 1=Qlo
            int rem  = slot & 1023;
            int r    = rem >> 3;
            int cB   = (rem & 7) * 16;
            const __half* src = arr ? QLO : QHI;
            cp16s(smU + (arr ? OFF_QLO : OFF_QHI) + (uint32_t)(r * 144 + cB),
                  src + base + (size_t)(q0 + r) * HDIM + (cB >> 1));
        }
        if (tid < 32)
            cp16s(smU + OFF_QM + (uint32_t)(tid * 16), mask + mrow + q0 + tid * 4);
    }
    load_tile(0, 0);   // commits the combined group

    const int r0l = warp * 16 + g;
    const int r1l = r0l + 8;
    const int srow0 = q0 + r0l, srow1 = q0 + r1l;

    const float NEGINF = __int_as_float(0xff800000u);
    float m0 = NEGINF, m1 = NEGINF, l0 = 0.f, l1 = 0.f;
    float acc[8][4];
#pragma unroll
    for (int i = 0; i < 8; i++)
#pragma unroll
        for (int j = 0; j < 4; j++) acc[i][j] = 0.f;

    // per-lane ldmatrix offsets (bytes, within an array of row-stride 144B)
    const uint32_t qoff = (uint32_t)((warp * 16 + (lane & 15)) * 144
                                     + (lane >> 4) * 16);
    const uint32_t koff = (uint32_t)((((lane >> 4) * 8) + (lane & 7)) * 144
                                     + ((lane >> 3) & 1) * 16);
    const uint32_t voff = (uint32_t)((lane & 15) * 144 + (lane >> 4) * 16);
    const uint32_t qhiB = smU + OFF_QHI + qoff;
    const uint32_t qloB = smU + OFF_QLO + qoff;

    const int* qm = (const int*)(smem_raw + OFF_QM);

    const int ntiles = (q0 + TQA) / TKA;
    for (int kt = 0; kt < ntiles; kt++) {
        const int t0 = kt * TKA;
        asm volatile("cp.async.wait_group 0;");
        __syncthreads();   // tile kt visible everywhere; prior compute done

        if (kt + 1 < ntiles) load_tile(t0 + TKA, (kt + 1) & 1);

        const uint32_t stb  = smU + OFF_STG + (uint32_t)(kt & 1) * STG_B;
        const uint32_t khiB = stb + koff;
        const uint32_t kloB = stb + 9216 + koff;
        const uint32_t vB   = stb + 18432 + voff;
        const int* km = (const int*)(smem_raw + OFF_KM + (kt & 1) * 256);

        // ---- QK via ldmatrix (fp16 2-term split, 3 mma)
        float sc[8][4];
#pragma unroll
        for (int i = 0; i < 8; i++)
#pragma unroll
            for (int j = 0; j < 4; j++) sc[i][j] = 0.f;

#pragma unroll
        for (int kj = 0; kj < 4; kj++) {
            uint32_t ah0, ah1, ah2, ah3, al0, al1, al2, al3;
            LDSM_X4(ah0, ah1, ah2, ah3, qhiB + kj * 32);
            LDSM_X4(al0, al1, al2, al3, qloB + kj * 32);
#pragma unroll
            for (int nfp = 0; nfp < 4; nfp++) {
                const uint32_t kk = (uint32_t)(nfp * 16 * 144 + kj * 32);
                uint32_t bh0, bh1, bh2, bh3, bl0, bl1, bl2, bl3;
                LDSM_X4(bh0, bh1, bh2, bh3, khiB + kk);
                LDSM_X4(bl0, bl1, bl2, bl3, kloB + kk);
                MMA16816(sc[2 * nfp],     ah0, ah1, ah2, ah3, bh0, bh1);
                MMA16816(sc[2 * nfp],     ah0, ah1, ah2, ah3, bl0, bl1);
                MMA16816(sc[2 * nfp],     al0, al1, al2, al3, bh0, bh1);
                MMA16816(sc[2 * nfp + 1], ah0, ah1, ah2, ah3, bh2, bh3);
                MMA16816(sc[2 * nfp + 1], ah0, ah1, ah2, ah3, bl2, bl3);
                MMA16816(sc[2 * nfp + 1], al0, al1, al2, al3, bh2, bh3);
            }
        }

        // ---- mask + online softmax (log2 domain, warp-local)
        const bool rm0 = (qm[r0l] != 0), rm1 = (qm[r1l] != 0);
        float mx0 = m0, mx1 = m1;
#pragma unroll
        for (int nf = 0; nf < 8; nf++) {
            const int c0i = nf * 8 + 2 * t, c1i = c0i + 1;
            const bool cm0 = (km[c0i] != 0), cm1 = (km[c1i] != 0);
            const int tc0 = t0 + c0i, tc1 = t0 + c1i;
            float v00 = (rm0 | cm0) ? 0.f : sc[nf][0]; if (tc0 > srow0) v00 = -1e30f;
            float v01 = (rm0 | cm1) ? 0.f : sc[nf][1]; if (tc1 > srow0) v01 = -1e30f;
            float v10 = (rm1 | cm0) ? 0.f : sc[nf][2]; if (tc0 > srow1) v10 = -1e30f;
            float v11 = (rm1 | cm1) ? 0.f : sc[nf][3]; if (tc1 > srow1) v11 = -1e30f;
            sc[nf][0] = v00; sc[nf][1] = v01; sc[nf][2] = v10; sc[nf][3] = v11;
            mx0 = fmaxf(mx0, fmaxf(v00, v01));
            mx1 = fmaxf(mx1, fmaxf(v10, v11));
        }
#pragma unroll
        for (int off = 1; off <= 2; off <<= 1) {
            mx0 = fmaxf(mx0, __shfl_xor_sync(0xffffffffu, mx0, off));
            mx1 = fmaxf(mx1, __shfl_xor_sync(0xffffffffu, mx1, off));
        }
        const float corr0 = ex2(m0 - mx0);
        const float corr1 = ex2(m1 - mx1);
        float rs0 = 0.f, rs1 = 0.f;
#pragma unroll
        for (int nf = 0; nf < 8; nf++) {
            float p00 = ex2(sc[nf][0] - mx0);
            float p01 = ex2(sc[nf][1] - mx0);
            float p10 = ex2(sc[nf][2] - mx1);
            float p11 = ex2(sc[nf][3] - mx1);
            sc[nf][0] = p00; sc[nf][1] = p01; sc[nf][2] = p10; sc[nf][3] = p11;
            rs0 += p00 + p01;
            rs1 += p10 + p11;
        }
#pragma unroll
        for (int off = 1; off <= 2; off <<= 1) {
            rs0 += __shfl_xor_sync(0xffffffffu, rs0, off);
            rs1 += __shfl_xor_sync(0xffffffffu, rs1, off);
        }
        l0 = l0 * corr0 + rs0;  m0 = mx0;
        l1 = l1 * corr1 + rs1;  m1 = mx1;
#pragma unroll
        for (int nfd = 0; nfd < 8; nfd++) {
            acc[nfd][0] *= corr0; acc[nfd][1] *= corr0;
            acc[nfd][2] *= corr1; acc[nfd][3] *= corr1;
        }

        // ---- PV: P (register re-pack) x V (ldmatrix.x4.trans)
#pragma unroll
        for (int kj = 0; kj < 4; kj++) {
            uint32_t a0 = pack_h2(sc[2 * kj][0],     sc[2 * kj][1]);
            uint32_t a1 = pack_h2(sc[2 * kj][2],     sc[2 * kj][3]);
            uint32_t a2 = pack_h2(sc[2 * kj + 1][0], sc[2 * kj + 1][1]);
            uint32_t a3 = pack_h2(sc[2 * kj + 1][2], sc[2 * kj + 1][3]);
            const uint32_t vrow = vB + (uint32_t)(kj * 16 * 144);
#pragma unroll
            for (int p = 0; p < 4; p++) {
                uint32_t b0, b1, b2, b3;
                LDSM_X4T(b0, b1, b2, b3, vrow + (uint32_t)(p * 32));
                MMA16816(acc[2 * p],     a0, a1, a2, a3, b0, b1);
                MMA16816(acc[2 * p + 1], a0, a1, a2, a3, b2, b3);
            }
        }
    }

    // ---- epilogue: normalize + tf32-round (feeds output GEMM directly)
    const float inv0 = 1.f / l0, inv1 = 1.f / l1;
#pragma unroll
    for (int nfd = 0; nfd < 8; nfd++) {
        const int dcol = nfd * 8 + 2 * t;
        *(float2*)(AO + base + (size_t)srow0 * HDIM + dcol) =
            make_float2(__uint_as_float(f2tf32(acc[nfd][0] * inv0)),
                        __uint_as_float(f2tf32(acc[nfd][1] * inv0)));
        *(float2*)(AO + base + (size_t)srow1 * HDIM + dcol) =
            make_float2(__uint_as_float(f2tf32(acc[nfd][2] * inv1)),
                        __uint_as_float(f2tf32(acc[nfd][3] * inv1)));
    }
}

// ---------------- launch -----------------------------------------------------
extern "C" void kernel_launch(void* const* d_in, const int* in_sizes, int n_in,
                              void* d_out, int out_size)
{
    const float* q    = (const float*)d_in[0];
    const float* k    = (const float*)d_in[1];
    const float* v    = (const float*)d_in[2];
    const float* Wq   = (const float*)d_in[3];
    const float* Wk   = (const float*)d_in[4];
    const float* Wv   = (const float*)d_in[5];
    const float* Wo   = (const float*)d_in[6];
    const int*   mask = (const int*)d_in[7];
    float* out = (float*)d_out;

    float* ao;
    unsigned *qt, *kt, *vt, *wq, *wk, *wv, *wo;
    __half *q16h, *q16l, *k16h, *k16l, *v16;
    cudaGetSymbolAddress((void**)&ao, g_ao);
    cudaGetSymbolAddress((void**)&qt, g_qt);
    cudaGetSymbolAddress((void**)&kt, g_kt);
    cudaGetSymbolAddress((void**)&vt, g_vt);
    cudaGetSymbolAddress((void**)&wq, g_wq);
    cudaGetSymbolAddress((void**)&wk, g_wk);
    cudaGetSymbolAddress((void**)&wv, g_wv);
    cudaGetSymbolAddress((void**)&wo, g_wo);
    cudaGetSymbolAddress((void**)&q16h, g_q16h);
    cudaGetSymbolAddress((void**)&q16l, g_q16l);
    cudaGetSymbolAddress((void**)&k16h, g_k16h);
    cudaGetSymbolAddress((void**)&k16l, g_k16l);
    cudaGetSymbolAddress((void**)&v16,  g_v16);

    // preconvert inputs + weights to tf32 (rna)
    dim3 gc(GM * GK / (256 * 4), 3);
    cvtqkv_kernel<<<gc, 256>>>(q, k, v);
    dim3 gw(GN * GK / (256 * 4), 4);
    cvtw_kernel<<<gw, 256>>>(Wq, Wk, Wv, Wo);

    cudaFuncSetAttribute(gemm3_kernel<0>,
                         cudaFuncAttributeMaxDynamicSharedMemorySize, GEMM_SMEM);
    cudaFuncSetAttribute(gemm3_kernel<1>,
                         cudaFuncAttributeMaxDynamicSharedMemorySize, GEMM_SMEM);

    // fused q/k/v projections -> fp16 hi/lo attention operands
    dim3 gp(GM / BM, GN / BN, 3);   // 32 x 8 x 3
    gemm3_kernel<0><<<gp, 256, GEMM_SMEM>>>(qt, kt, vt, wq, wk, wv,
                                            q16h, q16l, k16h, k16l, v16,
                                            nullptr);

    cudaFuncSetAttribute(attn_mma_kernel,
                         cudaFuncAttributeMaxDynamicSharedMemorySize, ATTN_SMEM);
    dim3 ga(SEQ / TQA, NHEAD, BATCH);   // 16 x 16 x 2
    attn_mma_kernel<<<ga, 256, ATTN_SMEM>>>(q16h, q16l, k16h, k16l, v16,
                                            mask, ao);

    // output projection: ao already tf32-rounded bits
    dim3 go(GM / BM, GN / BN, 1);
    gemm3_kernel<1><<<go, 256, GEMM_SMEM>>>((const unsigned*)ao, (const unsigned*)ao,
                                            (const unsigned*)ao, wo, wo, wo,
                                            nullptr, nullptr, nullptr, nullptr,
                                            nullptr, out);
}

// round 11
// speedup vs baseline: 3.9343x; 1.0150x over previous
#include <cuda_runtime.h>
#include <cuda_fp16.h>
#include <cstdint>

// Problem constants
#define BATCH   2
#define SEQ     2048
#define DIMM    1024
#define NHEAD   16
#define HDIM    64

#define GM 4096
#define GN 1024
#define GK 1024

#define QSCALE (0.125f * 1.44269504088896f)   // 1/sqrt(64) * log2(e)

// ---------------- scratch (allocation-free: device globals) ----------------
// tf32 pair-packed operands: AP[m][pc] = (x[m][8g+tq], x[m][8g+tq+4]), pc=4g+tq
static __device__ float2 g_apq[GM * (GK / 2)];
static __device__ float2 g_apk[GM * (GK / 2)];
static __device__ float2 g_apv[GM * (GK / 2)];
static __device__ float2 g_aop[GM * (GK / 2)];
// BP[pc][n] = (W[k1][n], W[k2][n]) with k1=8g+tq, k2=k1+4
static __device__ float2 g_bpq[(GK / 2) * GN];
static __device__ float2 g_bpk[(GK / 2) * GN];
static __device__ float2 g_bpv[(GK / 2) * GN];
static __device__ float2 g_bpo[(GK / 2) * GN];
// fp16 attention operands, [B,H,S,hd], written by projection GEMM epilogue
static __device__ __half g_q16h[BATCH * NHEAD * SEQ * HDIM];
static __device__ __half g_q16l[BATCH * NHEAD * SEQ * HDIM];
static __device__ __half g_k16h[BATCH * NHEAD * SEQ * HDIM];
static __device__ __half g_k16l[BATCH * NHEAD * SEQ * HDIM];
static __device__ __half g_v16 [BATCH * NHEAD * SEQ * HDIM];

// ---------------- helpers -----------------------------------------------------
__device__ __forceinline__ unsigned f2tf32(float x) {
    unsigned r;
    asm("cvt.rna.tf32.f32 %0, %1;" : "=r"(r) : "f"(x));
    return r;
}
__device__ __forceinline__ float tfr(float x) {          // tf32-rounded float
    return __uint_as_float(f2tf32(x));
}
__device__ __forceinline__ float ex2(float x) {
    float y;
    asm("ex2.approx.ftz.f32 %0, %1;" : "=f"(y) : "f"(x));
    return y;
}
__device__ __forceinline__ void cp16s(uint32_t smem_dst, const void* gmem_src) {
    asm volatile("cp.async.cg.shared.global [%0], [%1], 16;"
                 :: "r"(smem_dst), "l"(gmem_src));
}

// ---------------- preconvert kernels -----------------------------------------
// inputs q/k/v -> tf32 pair layout AP
__global__ __launch_bounds__(256)
void cvt_in_kernel(const float* __restrict__ q, const float* __restrict__ k,
                   const float* __restrict__ v)
{
    const float* s = (blockIdx.y == 0) ? q : (blockIdx.y == 1) ? k : v;
    float2* d = (blockIdx.y == 0) ? g_apq : (blockIdx.y == 1) ? g_apk : g_apv;
    int flat = blockIdx.x * 256 + threadIdx.x;   // 0 .. 4096*128-1
    int m  = flat >> 7;
    int g8 = flat & 127;
    const float* row = s + (size_t)m * GK + g8 * 8;
    float4 a = *(const float4*)row;
    float4 b = *(const float4*)(row + 4);
    float2* o = d + (size_t)m * (GK / 2) + g8 * 4;
    o[0] = make_float2(tfr(a.x), tfr(b.x));
    o[1] = make_float2(tfr(a.y), tfr(b.y));
    o[2] = make_float2(tfr(a.z), tfr(b.z));
    o[3] = make_float2(tfr(a.w), tfr(b.w));
}

// weights -> tf32 pair layout BP[pc][n]
__global__ __launch_bounds__(256)
void cvt_w_kernel(const float* __restrict__ Wq, const float* __restrict__ Wk,
                  const float* __restrict__ Wv, const float* __restrict__ Wo)
{
    const float* W;
    float2* o;
    switch (blockIdx.y) {
        case 0:  W = Wq; o = g_bpq; break;
        case 1:  W = Wk; o = g_bpk; break;
        case 2:  W = Wv; o = g_bpv; break;
        default: W = Wo; o = g_bpo; break;
    }
    int flat = blockIdx.x * 256 + threadIdx.x;   // 0 .. 512*512-1
    int pc = flat >> 9;
    int n2 = (flat & 511) * 2;
    int g8 = pc >> 2, tq = pc & 3;
    int k1 = 8 * g8 + tq, k2 = k1 + 4;
#pragma unroll
    for (int j = 0; j < 2; j++) {
        int n = n2 + j;
        float v1, v2;
        if (blockIdx.y < 3) {
            int hh = n >> 6, e = n & 63;
            v1 = W[((size_t)hh * GK + k1) * 64 + e];
            v2 = W[((size_t)hh * GK + k2) * 64 + e];
        } else {
            v1 = W[(size_t)k1 * GN + n];
            v2 = W[(size_t)k2 * GN + n];
        }
        o[(size_t)pc * GN + n] = make_float2(tfr(v1), tfr(v2));
    }
}

// ---------------- pair-packed tf32 GEMM: 128x128, BK=32, LDS.64 frags --------
// MODE 0: projection; z selects q/k/v; epilogue -> fp16 hi/lo [B,H,S,hd]
// MODE 1: plain GEMM -> f32 C.
#define BM 128
#define BN 128
#define BKK 32
#define AROW 160                       // bytes/row: 128 data + 32 pad
#define BROW 1088                      // bytes/row: 1024 data + 64 pad
#define ATILE (BM * AROW)              // 20480
#define STAGEB (ATILE + 16 * BROW)     // 37888
#define GEMM_SMEM (2 * STAGEB)         // 75776

template <int MODE>
__global__ __launch_bounds__(256, 2)
void gemm_kernel(const float2* __restrict__ A0, const float2* __restrict__ A1,
                 const float2* __restrict__ A2,
                 const float2* __restrict__ B0, const float2* __restrict__ B1,
                 const float2* __restrict__ B2,
                 __half* __restrict__ H0, __half* __restrict__ L0,
                 __half* __restrict__ H1, __half* __restrict__ L1,
                 __half* __restrict__ H2,
                 float* __restrict__ C)
{
    extern __shared__ char smraw[];
    const uint32_t smU = (uint32_t)__cvta_generic_to_shared(smraw);

    const int z = blockIdx.z;
    const float2* A = (z == 0) ? A0 : (z == 1) ? A1 : A2;
    const float2* B = (z == 0) ? B0 : (z == 1) ? B1 : B2;

    const int tid  = threadIdx.x;
    const int m0   = blockIdx.x * BM;
    const int n0   = blockIdx.y * BN;
    const int warp = tid >> 5;
    const int lane = tid & 31;
    const int warpM = warp & 1;          // 64-row halves
    const int warpN = warp >> 1;         // 32-col quarters
    const int g  = lane >> 2;
    const int tq = lane & 3;
    const int m0w = warpM * 64;
    const int n0w = warpN * 32;

    float acc[4][4][4];
#pragma unroll
    for (int i = 0; i < 4; i++)
#pragma unroll
        for (int j = 0; j < 4; j++)
#pragma unroll
            for (int r = 0; r < 4; r++) acc[i][j][r] = 0.f;

    auto load_tile = [&](int it, int s) {
        const int pc0 = it * 16;
        const uint32_t sb = smU + (uint32_t)s * STAGEB;
#pragma unroll
        for (int p = 0; p < 4; p++) {          // A: 1024 16B chunks
            int slot = tid + p * 256;
            int r = slot >> 3;                 // 0..127
            int c = slot & 7;                  // 0..7
            cp16s(sb + (uint32_t)(r * AROW + c * 16),
                  A + (size_t)(m0 + r) * (GK / 2) + pc0 + c * 2);
        }
#pragma unroll
        for (int p = 0; p < 4; p++) {          // B: 1024 16B chunks
            int slot = tid + p * 256;
            int r = slot >> 6;                 // 0..15
            int c = slot & 63;                 // 0..63
            cp16s(sb + (uint32_t)(ATILE + r * BROW + c * 16),
                  B + (size_t)(pc0 + r) * GN + n0 + c * 2);
        }
        asm volatile("cp.async.commit_group;");
    };

    const int NIT = GK / BKK;   // 32
    load_tile(0, 0);

    for (int it = 0; it < NIT; it++) {
        if (it + 1 < NIT) {
            load_tile(it + 1, (it + 1) & 1);
            asm volatile("cp.async.wait_group 1;");
        } else {
            asm volatile("cp.async.wait_group 0;");
        }
        __syncthreads();

        const char* sb = smraw + (it & 1) * STAGEB;
#pragma unroll
        for (int ks = 0; ks < 4; ks++) {
            const int pr = 4 * ks + tq;        // pair-row index
            float2 bf[4];
#pragma unroll
            for (int nf = 0; nf < 4; nf++)
                bf[nf] = *(const float2*)(sb + ATILE + pr * BROW
                                          + (n0w + nf * 8 + g) * 8);
#pragma unroll
            for (int mf = 0; mf < 4; mf++) {
                const char* ar = sb + (m0w + mf * 16 + g) * AROW + pr * 8;
                float2 alo = *(const float2*)ar;             // row g:   a0,a2
                float2 ahi = *(const float2*)(ar + 8 * AROW); // row g+8: a1,a3
#pragma unroll
                for (int nf = 0; nf < 4; nf++) {
                    asm volatile(
                        "mma.sync.aligned.m16n8k8.row.col.f32.tf32.tf32.f32 "
                        "{%0,%1,%2,%3}, {%4,%5,%6,%7}, {%8,%9}, {%0,%1,%2,%3};"
                        : "+f"(acc[mf][nf][0]), "+f"(acc[mf][nf][1]),
                          "+f"(acc[mf][nf][2]), "+f"(acc[mf][nf][3])
                        : "r"(__float_as_uint(alo.x)), "r"(__float_as_uint(ahi.x)),
                          "r"(__float_as_uint(alo.y)), "r"(__float_as_uint(ahi.y)),
                          "r"(__float_as_uint(bf[nf].x)), "r"(__float_as_uint(bf[nf].y)));
                }
            }
        }
        __syncthreads();
    }

    // ---- epilogue
    const float scl = (MODE == 0 && z == 0) ? QSCALE : 1.f;
    __half* OH = (z == 0) ? H0 : (z == 1) ? H1 : H2;
    __half* OL = (z == 0) ? L0 : L1;                 // unused for z==2
#pragma unroll
    for (int mf = 0; mf < 4; mf++) {
#pragma unroll
        for (int nf = 0; nf < 4; nf++) {
            const int gcol = n0 + n0w + nf * 8 + 2 * tq;
#pragma unroll
            for (int half = 0; half < 2; half++) {
                const int grow = m0 + m0w + mf * 16 + g + half * 8;
                float x0 = acc[mf][nf][half * 2]     * scl;
                float x1 = acc[mf][nf][half * 2 + 1] * scl;
                if (MODE == 0) {
                    const int bb = grow >> 11, ss = grow & 2047;
                    const int hh = gcol >> 6, e = gcol & 63;
                    const size_t idx =
                        (((size_t)(bb * NHEAD + hh)) * SEQ + ss) * HDIM + e;
                    __half h0 = __float2half_rn(x0);
                    __half h1 = __float2half_rn(x1);
                    __half2 hv; hv.x = h0; hv.y = h1;
                    *(__half2*)(OH + idx) = hv;
                    if (z < 2) {
                        __half l0 = __float2half_rn(x0 - __half2float(h0));
                        __half l1 = __float2half_rn(x1 - __half2float(h1));
                        __half2 lv; lv.x = l0; lv.y = l1;
                        *(__half2*)(OL + idx) = lv;
                    }
                } else {
                    *(float2*)(C + (size_t)grow * GN + gcol) =
                        make_float2(x0, x1);
                }
            }
        }
    }
}

// ================= MMA flash attention: direct fp16 tiles ===================
#define TQA 128
#define TKA 64

// smem (bytes): Qhi 18432 | Qlo 18432 | stage0 27648 | stage1 27648 | qm 512 | km 512
#define OFF_QHI 0
#define OFF_QLO 18432
#define OFF_STG 36864
#define STG_B   27648     // Khi 9216 + Klo 9216 + V 9216
#define OFF_QM  92160
#define OFF_KM  92672
#define ATTN_SMEM 93696

#define MMA16816(CC, A0, A1, A2, A3, B0, B1)                                  \
    asm volatile(                                                             \
        "mma.sync.aligned.m16n8k16.row.col.f32.f16.f16.f32 "                  \
        "{%0,%1,%2,%3}, {%4,%5,%6,%7}, {%8,%9}, {%0,%1,%2,%3};"               \
        : "+f"((CC)[0]), "+f"((CC)[1]), "+f"((CC)[2]), "+f"((CC)[3])          \
        : "r"(A0), "r"(A1), "r"(A2), "r"(A3), "r"(B0), "r"(B1))

#define LDSM_X4(R0, R1, R2, R3, ADDR)                                         \
    asm volatile("ldmatrix.sync.aligned.m8n8.x4.shared.b16 {%0,%1,%2,%3}, [%4];" \
                 : "=r"(R0), "=r"(R1), "=r"(R2), "=r"(R3) : "r"(ADDR))

#define LDSM_X4T(R0, R1, R2, R3, ADDR)                                        \
    asm volatile("ldmatrix.sync.aligned.m8n8.x4.trans.shared.b16 {%0,%1,%2,%3}, [%4];" \
                 : "=r"(R0), "=r"(R1), "=r"(R2), "=r"(R3) : "r"(ADDR))

__device__ __forceinline__ uint32_t pack_h2(float a, float b) {
    __half2 h = __floats2half2_rn(a, b);
    return *(uint32_t*)&h;
}

__global__ __launch_bounds__(256, 2)
void attn_mma_kernel(const __half* __restrict__ QHI, const __half* __restrict__ QLO,
                     const __half* __restrict__ KHI, const __half* __restrict__ KLO,
                     const __half* __restrict__ V16, const int* __restrict__ mask,
                     float2* __restrict__ AOP)
{
    extern __shared__ char smem_raw[];
    const uint32_t smU = (uint32_t)__cvta_generic_to_shared(smem_raw);

    const int b = blockIdx.z, h = blockIdx.y;
    const int qt = (int)gridDim.x - 1 - (int)blockIdx.x;   // heavy tiles first
    const int q0 = qt * TQA;
    const size_t base = ((size_t)(b * NHEAD + h)) * SEQ * HDIM;
    const int mrow = b * SEQ;

    const int tid  = threadIdx.x;
    const int warp = tid >> 5, lane = tid & 31;
    const int g = lane >> 2, t = lane & 3;

    // ---- tile loader: stage s <- k-tile starting at t0n (K hi/lo + V + km)
    auto load_tile = [&](int t0n, int s) {
        const uint32_t sb = smU + OFF_STG + (uint32_t)s * STG_B;
#pragma unroll
        for (int p = 0; p < 6; p++) {
            int slot = tid + p * 256;            // 0..1535
            int arr  = slot >> 9;                // 0=Khi 1=Klo 2=V
            int rem  = slot & 511;
            int r    = rem >> 3;
            int cB   = (rem & 7) * 16;
            const __half* src = (arr == 0) ? KHI : (arr == 1) ? KLO : V16;
            cp16s(sb + (uint32_t)(arr * 9216 + r * 144 + cB),
                  src + base + (size_t)(t0n + r) * HDIM + (cB >> 1));
        }
        if (tid < 16)
            cp16s(smU + OFF_KM + (uint32_t)(s * 256 + tid * 16),
                  mask + mrow + t0n + tid * 4);
        asm volatile("cp.async.commit_group;");
    };

    // ---- prologue: Q hi/lo + qm + tile 0, one group
    {
#pragma unroll
        for (int p = 0; p < 8; p++) {
            int slot = tid + p * 256;            // 0..2047
            int arr  = slot >> 10;               // 0=Qhi 1=Qlo
            int rem  = slot & 1023;
            int r    = rem >> 3;
            int cB   = (rem & 7) * 16;
            const __half* src = arr ? QLO : QHI;
            cp16s(smU + (arr ? OFF_QLO : OFF_QHI) + (uint32_t)(r * 144 + cB),
                  src + base + (size_t)(q0 + r) * HDIM + (cB >> 1));
        }
        if (tid < 32)
            cp16s(smU + OFF_QM + (uint32_t)(tid * 16), mask + mrow + q0 + tid * 4);
    }
    load_tile(0, 0);

    const int r0l = warp * 16 + g;
    const int r1l = r0l + 8;
    const int srow0 = q0 + r0l, srow1 = q0 + r1l;

    const float NEGINF = __int_as_float(0xff800000u);
    float m0 = NEGINF, m1 = NEGINF, l0 = 0.f, l1 = 0.f;
    float acc[8][4];
#pragma unroll
    for (int i = 0; i < 8; i++)
#pragma unroll
        for (int j = 0; j < 4; j++) acc[i][j] = 0.f;

    const uint32_t qoff = (uint32_t)((warp * 16 + (lane & 15)) * 144
                                     + (lane >> 4) * 16);
    const uint32_t koff = (uint32_t)((((lane >> 4) * 8) + (lane & 7)) * 144
                                     + ((lane >> 3) & 1) * 16);
    const uint32_t voff = (uint32_t)((lane & 15) * 144 + (lane >> 4) * 16);
    const uint32_t qhiB = smU + OFF_QHI + qoff;
    const uint32_t qloB = smU + OFF_QLO + qoff;

    const int* qm = (const int*)(smem_raw + OFF_QM);

    const int ntiles = (q0 + TQA) / TKA;
    for (int kt = 0; kt < ntiles; kt++) {
        const int t0 = kt * TKA;
        asm volatile("cp.async.wait_group 0;");
        __syncthreads();

        if (kt + 1 < ntiles) load_tile(t0 + TKA, (kt + 1) & 1);

        const uint32_t stb  = smU + OFF_STG + (uint32_t)(kt & 1) * STG_B;
        const uint32_t khiB = stb + koff;
        const uint32_t kloB = stb + 9216 + koff;
        const uint32_t vB   = stb + 18432 + voff;
        const int* km = (const int*)(smem_raw + OFF_KM + (kt & 1) * 256);

        // ---- QK via ldmatrix (fp16 2-term split, 3 mma)
        float sc[8][4];
#pragma unroll
        for (int i = 0; i < 8; i++)
#pragma unroll
            for (int j = 0; j < 4; j++) sc[i][j] = 0.f;

#pragma unroll
        for (int kj = 0; kj < 4; kj++) {
            uint32_t ah0, ah1, ah2, ah3, al0, al1, al2, al3;
            LDSM_X4(ah0, ah1, ah2, ah3, qhiB + kj * 32);
            LDSM_X4(al0, al1, al2, al3, qloB + kj * 32);
#pragma unroll
            for (int nfp = 0; nfp < 4; nfp++) {
                const uint32_t kk = (uint32_t)(nfp * 16 * 144 + kj * 32);
                uint32_t bh0, bh1, bh2, bh3, bl0, bl1, bl2, bl3;
                LDSM_X4(bh0, bh1, bh2, bh3, khiB + kk);
                LDSM_X4(bl0, bl1, bl2, bl3, kloB + kk);
                MMA16816(sc[2 * nfp],     ah0, ah1, ah2, ah3, bh0, bh1);
                MMA16816(sc[2 * nfp],     ah0, ah1, ah2, ah3, bl0, bl1);
                MMA16816(sc[2 * nfp],     al0, al1, al2, al3, bh0, bh1);
                MMA16816(sc[2 * nfp + 1], ah0, ah1, ah2, ah3, bh2, bh3);
                MMA16816(sc[2 * nfp + 1], ah0, ah1, ah2, ah3, bl2, bl3);
                MMA16816(sc[2 * nfp + 1], al0, al1, al2, al3, bh2, bh3);
            }
        }

        // ---- mask + online softmax (log2 domain, warp-local)
        const bool rm0 = (qm[r0l] != 0), rm1 = (qm[r1l] != 0);
        float mx0 = m0, mx1 = m1;
        if (t0 + TKA > q0) {
            // diagonal region: causal masking applies
#pragma unroll
            for (int nf = 0; nf < 8; nf++) {
                const int c0i = nf * 8 + 2 * t, c1i = c0i + 1;
                const bool cm0 = (km[c0i] != 0), cm1 = (km[c1i] != 0);
                const int tc0 = t0 + c0i, tc1 = t0 + c1i;
                float v00 = (rm0 | cm0) ? 0.f : sc[nf][0]; if (tc0 > srow0) v00 = -1e30f;
                float v01 = (rm0 | cm1) ? 0.f : sc[nf][1]; if (tc1 > srow0) v01 = -1e30f;
                float v10 = (rm1 | cm0) ? 0.f : sc[nf][2]; if (tc0 > srow1) v10 = -1e30f;
                float v11 = (rm1 | cm1) ? 0.f : sc[nf][3]; if (tc1 > srow1) v11 = -1e30f;
                sc[nf][0] = v00; sc[nf][1] = v01; sc[nf][2] = v10; sc[nf][3] = v11;
                mx0 = fmaxf(mx0, fmaxf(v00, v01));
                mx1 = fmaxf(mx1, fmaxf(v10, v11));
            }
        } else {
            // strictly-past tiles: no causal compare needed
#pragma unroll
            for (int nf = 0; nf < 8; nf++) {
                const int c0i = nf * 8 + 2 * t, c1i = c0i + 1;
                const bool cm0 = (km[c0i] != 0), cm1 = (km[c1i] != 0);
                float v00 = (rm0 | cm0) ? 0.f : sc[nf][0];
                float v01 = (rm0 | cm1) ? 0.f : sc[nf][1];
                float v10 = (rm1 | cm0) ? 0.f : sc[nf][2];
                float v11 = (rm1 | cm1) ? 0.f : sc[nf][3];
                sc[nf][0] = v00; sc[nf][1] = v01; sc[nf][2] = v10; sc[nf][3] = v11;
                mx0 = fmaxf(mx0, fmaxf(v00, v01));
                mx1 = fmaxf(mx1, fmaxf(v10, v11));
            }
        }
#pragma unroll
        for (int off = 1; off <= 2; off <<= 1) {
            mx0 = fmaxf(mx0, __shfl_xor_sync(0xffffffffu, mx0, off));
            mx1 = fmaxf(mx1, __shfl_xor_sync(0xffffffffu, mx1, off));
        }
        const float corr0 = ex2(m0 - mx0);
        const float corr1 = ex2(m1 - mx1);
        float rs0 = 0.f, rs1 = 0.f;
#pragma unroll
        for (int nf = 0; nf < 8; nf++) {
            float p00 = ex2(sc[nf][0] - mx0);
            float p01 = ex2(sc[nf][1] - mx0);
            float p10 = ex2(sc[nf][2] - mx1);
            float p11 = ex2(sc[nf][3] - mx1);
            sc[nf][0] = p00; sc[nf][1] = p01; sc[nf][2] = p10; sc[nf][3] = p11;
            rs0 += p00 + p01;
            rs1 += p10 + p11;
        }
#pragma unroll
        for (int off = 1; off <= 2; off <<= 1) {
            rs0 += __shfl_xor_sync(0xffffffffu, rs0, off);
            rs1 += __shfl_xor_sync(0xffffffffu, rs1, off);
        }
        l0 = l0 * corr0 + rs0;  m0 = mx0;
        l1 = l1 * corr1 + rs1;  m1 = mx1;
#pragma unroll
        for (int nfd = 0; nfd < 8; nfd++) {
            acc[nfd][0] *= corr0; acc[nfd][1] *= corr0;
            acc[nfd][2] *= corr1; acc[nfd][3] *= corr1;
        }

        // ---- PV: P (register re-pack) x V (ldmatrix.x4.trans)
#pragma unroll
        for (int kj = 0; kj < 4; kj++) {
            uint32_t a0 = pack_h2(sc[2 * kj][0],     sc[2 * kj][1]);
            uint32_t a1 = pack_h2(sc[2 * kj][2],     sc[2 * kj][3]);
            uint32_t a2 = pack_h2(sc[2 * kj + 1][0], sc[2 * kj + 1][1]);
            uint32_t a3 = pack_h2(sc[2 * kj + 1][2], sc[2 * kj + 1][3]);
            const uint32_t vrow = vB + (uint32_t)(kj * 16 * 144);
#pragma unroll
            for (int p = 0; p < 4; p++) {
                uint32_t b0, b1, b2, b3;
                LDSM_X4T(b0, b1, b2, b3, vrow + (uint32_t)(p * 32));
                MMA16816(acc[2 * p],     a0, a1, a2, a3, b0, b1);
                MMA16816(acc[2 * p + 1], a0, a1, a2, a3, b2, b3);
            }
        }
    }

    // ---- epilogue: normalize + tf32-round, write pair layout for Wo GEMM
    // thread's cols: k = nfd*8 + 2t, 2t+1. pair-col = 4*nfd + (2t&3), component t>>1
    const float inv0 = 1.f / l0, inv1 = 1.f / l1;
    float* AO = (float*)AOP;
#pragma unroll
    for (int nfd = 0; nfd < 8; nfd++) {
        const int pcb  = 4 * nfd + ((2 * t) & 3);
        const int comp = t >> 1;
        const size_t i00 = ((base + (size_t)srow0 * HDIM) + pcb * 2) + comp;
        const size_t i10 = ((base + (size_t)srow1 * HDIM) + pcb * 2) + comp;
        AO[i00]     = tfr(acc[nfd][0] * inv0);
        AO[i00 + 2] = tfr(acc[nfd][1] * inv0);
        AO[i10]     = tfr(acc[nfd][2] * inv1);
        AO[i10 + 2] = tfr(acc[nfd][3] * inv1);
    }
}

// ---------------- launch -----------------------------------------------------
extern "C" void kernel_launch(void* const* d_in, const int* in_sizes, int n_in,
                              void* d_out, int out_size)
{
    const float* q    = (const float*)d_in[0];
    const float* k    = (const float*)d_in[1];
    const float* v    = (const float*)d_in[2];
    const float* Wq   = (const float*)d_in[3];
    const float* Wk   = (const float*)d_in[4];
    const float* Wv   = (const float*)d_in[5];
    const float* Wo   = (const float*)d_in[6];
    const int*   mask = (const int*)d_in[7];
    float* out = (float*)d_out;

    float2 *apq, *apk, *apv, *aop, *bpq, *bpk, *bpv, *bpo;
    __half *q16h, *q16l, *k16h, *k16l, *v16;
    cudaGetSymbolAddress((void**)&apq, g_apq);
    cudaGetSymbolAddress((void**)&apk, g_apk);
    cudaGetSymbolAddress((void**)&apv, g_apv);
    cudaGetSymbolAddress((void**)&aop, g_aop);
    cudaGetSymbolAddress((void**)&bpq, g_bpq);
    cudaGetSymbolAddress((void**)&bpk, g_bpk);
    cudaGetSymbolAddress((void**)&bpv, g_bpv);
    cudaGetSymbolAddress((void**)&bpo, g_bpo);
    cudaGetSymbolAddress((void**)&q16h, g_q16h);
    cudaGetSymbolAddress((void**)&q16l, g_q16l);
    cudaGetSymbolAddress((void**)&k16h, g_k16h);
    cudaGetSymbolAddress((void**)&k16l, g_k16l);
    cudaGetSymbolAddress((void**)&v16,  g_v16);

    // preconvert inputs + weights to tf32 pair layout
    dim3 gc(GM * (GK / 8) / 256, 3);    // 2048 x 3
    cvt_in_kernel<<<gc, 256>>>(q, k, v);
    dim3 gw((GK / 2) * (GN / 2) / 256, 4);  // 1024 x 4
    cvt_w_kernel<<<gw, 256>>>(Wq, Wk, Wv, Wo);

    cudaFuncSetAttribute(gemm_kernel<0>,
                         cudaFuncAttributeMaxDynamicSharedMemorySize, GEMM_SMEM);
    cudaFuncSetAttribute(gemm_kernel<1>,
                         cudaFuncAttributeMaxDynamicSharedMemorySize, GEMM_SMEM);

    // fused q/k/v projections -> fp16 hi/lo attention operands
    dim3 gp(GM / BM, GN / BN, 3);   // 32 x 8 x 3
    gemm_kernel<0><<<gp, 256, GEMM_SMEM>>>(apq, apk, apv, bpq, bpk, bpv,
                                           q16h, q16l, k16h, k16l, v16,
                                           nullptr);

    cudaFuncSetAttribute(attn_mma_kernel,
                         cudaFuncAttributeMaxDynamicSharedMemorySize, ATTN_SMEM);
    dim3 ga(SEQ / TQA, NHEAD, BATCH);   // 16 x 16 x 2
    attn_mma_kernel<<<ga, 256, ATTN_SMEM>>>(q16h, q16l, k16h, k16l, v16,
                                            mask, aop);

    // output projection: aop already tf32-rounded pair layout
    dim3 go(GM / BM, GN / BN, 1);
    gemm_kernel<1><<<go, 256, GEMM_SMEM>>>(aop, aop, aop, bpo, bpo, bpo,
                                           nullptr, nullptr, nullptr, nullptr,
                                           nullptr, out);
}